// round 12
// baseline (speedup 1.0000x reference)
#include <cuda_runtime.h>
#include <cuda_fp16.h>
#include <math.h>

#define BN 16
#define CN 256
#define NN 4096          // H*W
#define HEADS 4
#define HD 64
#define GROUPS 4

// ---------------- scratch (__device__ globals: allocation-free) ----------------
__device__ __align__(128) __half g_convh[4][BN * CN * NN]; // conv outputs fp16
__device__ float g_fused[BN * CN * NN];     // fused (fp32, v path)
__device__ __align__(128) __half g_fa[BN * CN * NN];       // fused fp16 (GEMM A)
__device__ __align__(128) __half g_wth[256 * 512];         // qk_w^T fp16: [k][j]
__device__ float g_qp[BN * CN * NN];
__device__ float g_kp[BN * CN * NN];
__device__ float g_qr[BN * CN * NN];
__device__ float g_kr[BN * CN * NN];
__device__ float g_kmean[BN * CN];
__device__ float g_z[BN * HEADS * NN];
__device__ float g_kv[BN * HEADS * HD * HD];
__device__ float g_cos[64 * 128];
__device__ float g_sin[64 * 128];
__device__ float g_fw[4];
__device__ float g_ssum[4 * BN * GROUPS];
__device__ float g_ssq[4 * BN * GROUPS];

// ---------------- K0: init ----------------
__global__ void k_init(const float* __restrict__ fusion_w) {
    int idx = blockIdx.x * 256 + threadIdx.x;
    if (idx < BN * HEADS * HD * HD) g_kv[idx] = 0.f;
    if (idx < 4 * BN * GROUPS) { g_ssum[idx] = 0.f; g_ssq[idx] = 0.f; }
    if (idx < 64 * 128) {
        int w = idx / 128, k = idx % 128;
        float theta = powf(10000.f, -(float)k / 128.f);
        float ang = (float)w * theta;
        g_cos[idx] = cosf(ang);
        g_sin[idx] = sinf(ang);
    }
    if (idx == 0) {
        float m = fusion_w[0];
        for (int i = 1; i < 4; i++) m = fmaxf(m, fusion_w[i]);
        float e[4], s = 0.f;
        for (int i = 0; i < 4; i++) { e[i] = expf(fusion_w[i] - m); s += e[i]; }
        for (int i = 0; i < 4; i++) g_fw[i] = e[i] / s;
    }
}

// ---------------- transpose qk_w [512,256] -> g_wth [256][512] fp16 ----------------
__global__ void k_wtrans(const float* __restrict__ qkw) {
    int id = blockIdx.x * 256 + threadIdx.x;   // 512*256 total
    int k = id / 512, j = id % 512;
    g_wth[id] = __float2half(qkw[j * 256 + k]);
}

// ---------------- K1: all 4 depthwise convs fused, one tile load ----------------
__global__ __launch_bounds__(256) void k_conv4(
    const float* __restrict__ x,
    const float* __restrict__ w3, const float* __restrict__ b3,
    const float* __restrict__ w5, const float* __restrict__ b5,
    const float* __restrict__ w7, const float* __restrict__ b7,
    const float* __restrict__ w9, const float* __restrict__ b9) {
    __shared__ float tile[72 * 72];
    __shared__ float ws3[9], ws5[25], ws7[49], ws9[81];
    __shared__ float rsum[4][8], rsq[4][8];
    const int c = blockIdx.x, b = blockIdx.y;
    const int tid = threadIdx.x;
    const size_t plane = ((size_t)(b * CN + c)) * NN;
    const float* xp = x + plane;
    for (int i = tid; i < 72 * 72; i += 256) {
        int ty = i / 72, tx = i % 72;
        int gy = ty - 4, gx = tx - 4;
        float v = 0.f;
        if (gy >= 0 && gy < 64 && gx >= 0 && gx < 64) v = xp[gy * 64 + gx];
        tile[i] = v;
    }
    if (tid < 9)  ws3[tid] = w3[c * 9 + tid];
    if (tid < 25) ws5[tid] = w5[c * 25 + tid];
    if (tid < 49) ws7[tid] = w7[c * 49 + tid];
    if (tid < 81) ws9[tid] = w9[c * 81 + tid];
    __syncthreads();

    const float bv[4] = {b3[c], b5[c], b7[c], b9[c]};
    float s[4] = {0.f, 0.f, 0.f, 0.f}, q[4] = {0.f, 0.f, 0.f, 0.f};

#pragma unroll
    for (int seg = 0; seg < 2; seg++) {
        int sidx = tid + seg * 256;
        int h = sidx / 8;
        int w0 = (sidx % 8) * 8;
        float a[4][8];
#pragma unroll
        for (int br = 0; br < 4; br++)
#pragma unroll
            for (int j = 0; j < 8; j++) a[br][j] = bv[br];

#pragma unroll
        for (int dy = 0; dy < 9; dy++) {
            const float* trow = &tile[(h + dy) * 72 + w0];
            float rv[16];
#pragma unroll
            for (int xi = 0; xi < 16; xi++) rv[xi] = trow[xi];
            // k9 (pad 4): rows 0..8, cols rv[dx + j]
#pragma unroll
            for (int dx = 0; dx < 9; dx++) {
                float wv = ws9[dy * 9 + dx];
#pragma unroll
                for (int j = 0; j < 8; j++) a[3][j] = fmaf(rv[dx + j], wv, a[3][j]);
            }
            if (dy >= 1 && dy <= 7) {   // k7
                int d7 = dy - 1;
#pragma unroll
                for (int dx = 0; dx < 7; dx++) {
                    float wv = ws7[d7 * 7 + dx];
#pragma unroll
                    for (int j = 0; j < 8; j++) a[2][j] = fmaf(rv[dx + 1 + j], wv, a[2][j]);
                }
            }
            if (dy >= 2 && dy <= 6) {   // k5
                int d5 = dy - 2;
#pragma unroll
                for (int dx = 0; dx < 5; dx++) {
                    float wv = ws5[d5 * 5 + dx];
#pragma unroll
                    for (int j = 0; j < 8; j++) a[1][j] = fmaf(rv[dx + 2 + j], wv, a[1][j]);
                }
            }
            if (dy >= 3 && dy <= 5) {   // k3
                int d3 = dy - 3;
#pragma unroll
                for (int dx = 0; dx < 3; dx++) {
                    float wv = ws3[d3 * 3 + dx];
#pragma unroll
                    for (int j = 0; j < 8; j++) a[0][j] = fmaf(rv[dx + 3 + j], wv, a[0][j]);
                }
            }
        }

#pragma unroll
        for (int br = 0; br < 4; br++) {
            __half2 hh[4];
#pragma unroll
            for (int t = 0; t < 4; t++) hh[t] = __floats2half2_rn(a[br][2 * t], a[br][2 * t + 1]);
            *(uint4*)(&g_convh[br][plane + h * 64 + w0]) = *(uint4*)hh;
#pragma unroll
            for (int j = 0; j < 8; j++) { s[br] += a[br][j]; q[br] = fmaf(a[br][j], a[br][j], q[br]); }
        }
    }

    int warp = tid / 32, lane = tid % 32;
#pragma unroll
    for (int br = 0; br < 4; br++) {
        float ss = s[br], qq = q[br];
        for (int o = 16; o > 0; o >>= 1) {
            ss += __shfl_down_sync(~0u, ss, o);
            qq += __shfl_down_sync(~0u, qq, o);
        }
        if (lane == 0) { rsum[br][warp] = ss; rsq[br][warp] = qq; }
    }
    __syncthreads();
    if (tid < 4) {
        float ts = 0.f, tq = 0.f;
        for (int i = 0; i < 8; i++) { ts += rsum[tid][i]; tq += rsq[tid][i]; }
        int g = c >> 6;
        atomicAdd(&g_ssum[(tid * BN + b) * GROUPS + g], ts);
        atomicAdd(&g_ssq [(tid * BN + b) * GROUPS + g], tq);
    }
}

// ---------------- K2: groupnorm + sigmoid + weighted fuse (fp16 in, fp32+fp16 out) ----------------
__global__ void k_fuse(const float* __restrict__ gn_w, const float* __restrict__ gn_b) {
    int idx8 = blockIdx.x * 256 + threadIdx.x;   // uint4-of-halfs index (8 elems)
    int base = idx8 * 8;
    int b = base / (CN * NN);
    int c = (base / NN) % CN;
    int g = c >> 6;
    const float cnt = 64.f * 4096.f;
    float res[8];
#pragma unroll
    for (int t = 0; t < 8; t++) res[t] = 0.f;
#pragma unroll
    for (int br = 0; br < 4; br++) {
        float sS  = g_ssum[(br * BN + b) * GROUPS + g];
        float sq = g_ssq [(br * BN + b) * GROUPS + g];
        float mean = sS / cnt;
        float var = sq / cnt - mean * mean;
        float rstd = rsqrtf(var + 1e-5f);
        float gamma = gn_w[br * CN + c] * rstd;
        float beta = gn_b[br * CN + c] - mean * gamma;
        float wt = g_fw[br];
        uint4 raw = *(const uint4*)(&g_convh[br][base]);
        const __half2* h2 = (const __half2*)&raw;
#pragma unroll
        for (int t = 0; t < 4; t++) {
            float2 f = __half22float2(h2[t]);
            res[2 * t]     += wt / (1.f + __expf(-(f.x * gamma + beta)));
            res[2 * t + 1] += wt / (1.f + __expf(-(f.y * gamma + beta)));
        }
    }
    *(float4*)(g_fused + base)     = make_float4(res[0], res[1], res[2], res[3]);
    *(float4*)(g_fused + base + 4) = make_float4(res[4], res[5], res[6], res[7]);
    __half2 hh[4];
#pragma unroll
    for (int t = 0; t < 4; t++) hh[t] = __floats2half2_rn(res[2 * t], res[2 * t + 1]);
    *(uint4*)(&g_fa[base]) = *(uint4*)hh;
}

// ---------------- tensor-core helpers ----------------
__device__ __forceinline__ unsigned s2u(const void* p) {
    return (unsigned)__cvta_generic_to_shared(p);
}
__device__ __forceinline__ void cpa16(unsigned dst, const void* src) {
    asm volatile("cp.async.cg.shared.global [%0], [%1], 16;" :: "r"(dst), "l"(src));
}
__device__ __forceinline__ void cpcommit() {
    asm volatile("cp.async.commit_group;");
}
template <int N>
__device__ __forceinline__ void cpwait() {
    asm volatile("cp.async.wait_group %0;" :: "n"(N));
}
__device__ __forceinline__ void ldsm4t(unsigned* r, unsigned addr) {
    asm volatile("ldmatrix.sync.aligned.m8n8.x4.trans.shared.b16 {%0,%1,%2,%3}, [%4];"
        : "=r"(r[0]), "=r"(r[1]), "=r"(r[2]), "=r"(r[3]) : "r"(addr));
}
__device__ __forceinline__ void mma16816(float* c, const unsigned* a, const unsigned* b) {
    asm volatile(
        "mma.sync.aligned.m16n8k16.row.col.f32.f16.f16.f32 "
        "{%0,%1,%2,%3}, {%4,%5,%6,%7}, {%8,%9}, {%0,%1,%2,%3};"
        : "+f"(c[0]), "+f"(c[1]), "+f"(c[2]), "+f"(c[3])
        : "r"(a[0]), "r"(a[1]), "r"(a[2]), "r"(a[3]), "r"(b[0]), "r"(b[1]));
}

// ---------------- K3: QK GEMM fp16 mma + elu + RoPE epilogue ----------------
// block 128(m tokens) x 128(n chans), full K=256 resident in smem, cp.async staged.
#define GPITCH 136   // halfs per smem row (128 + 8 pad)
__global__ __launch_bounds__(256) void k_gemm_tc(void) {
    extern __shared__ __align__(16) __half sm[];
    __half* As = sm;                 // [256 k][GPITCH m]
    __half* Bs = sm + 256 * GPITCH;  // [256 k][GPITCH j]

    const int tid = threadIdx.x;
    const int warp = tid >> 5;
    const int lane = tid & 31;
    const int gid = lane >> 2, tig = lane & 3;
    const int wm = warp & 3;     // 4 m-tiles of 32
    const int wn = warp >> 2;    // 2 n-tiles of 64

    const int m0 = blockIdx.x * 128;
    const int j0 = blockIdx.y * 128;
    const int bidx = m0 / NN;
    const int ntok = m0 % NN;

    // ---- issue all loads: 8 groups of K=32 rows each (A + B) ----
    const unsigned sA = s2u(As), sB = s2u(Bs);
    const __half* srcA = g_fa + (size_t)bidx * CN * NN + ntok;
#pragma unroll
    for (int g = 0; g < 8; g++) {
#pragma unroll
        for (int rep = 0; rep < 2; rep++) {
            int cidx = tid + rep * 256;          // 0..511
            int kl = g * 32 + (cidx >> 4);
            int off = (cidx & 15) * 8;
            cpa16(sA + (kl * GPITCH + off) * 2, srcA + (size_t)kl * NN + off);
            cpa16(sB + (kl * GPITCH + off) * 2, g_wth + kl * 512 + j0 + off);
        }
        cpcommit();
    }

    // ---- ldmatrix address precompute ----
    const int l8 = lane >> 3, r8 = lane & 7;
    const int a_kr = r8 + ((l8 >> 1) << 3);
    const int a_mc = (l8 & 1) << 3;
    const int b_kr = r8 + ((l8 & 1) << 3);
    const int b_nc = (l8 >> 1) << 3;
    unsigned aaddr[2], baddr[4];
#pragma unroll
    for (int fm = 0; fm < 2; fm++)
        aaddr[fm] = sA + (a_kr * GPITCH + wm * 32 + fm * 16 + a_mc) * 2;
#pragma unroll
    for (int p = 0; p < 4; p++)
        baddr[p] = sB + (b_kr * GPITCH + wn * 64 + p * 16 + b_nc) * 2;

    float acc[2][8][4];
#pragma unroll
    for (int fm = 0; fm < 2; fm++)
#pragma unroll
        for (int fn = 0; fn < 8; fn++)
#pragma unroll
            for (int t = 0; t < 4; t++) acc[fm][fn][t] = 0.f;

    // ---- staged compute: wait group kt, compute its two k16 slices ----
#pragma unroll
    for (int kt = 0; kt < 8; kt++) {
        switch (kt) {
            case 0: cpwait<7>(); break; case 1: cpwait<6>(); break;
            case 2: cpwait<5>(); break; case 3: cpwait<4>(); break;
            case 4: cpwait<3>(); break; case 5: cpwait<2>(); break;
            case 6: cpwait<1>(); break; default: cpwait<0>(); break;
        }
        __syncthreads();
#pragma unroll
        for (int h16 = 0; h16 < 2; h16++) {
            const unsigned koff = (unsigned)(kt * 32 + h16 * 16) * (GPITCH * 2);
            unsigned a[2][4], b[8][2];
            ldsm4t(a[0], aaddr[0] + koff);
            ldsm4t(a[1], aaddr[1] + koff);
#pragma unroll
            for (int p = 0; p < 4; p++) {
                unsigned t[4];
                ldsm4t(t, baddr[p] + koff);
                b[2 * p][0] = t[0]; b[2 * p][1] = t[1];
                b[2 * p + 1][0] = t[2]; b[2 * p + 1][1] = t[3];
            }
#pragma unroll
            for (int fm = 0; fm < 2; fm++)
#pragma unroll
                for (int fn = 0; fn < 8; fn++)
                    mma16816(acc[fm][fn], a[fm], b[fn]);
        }
    }

    // ---- epilogue: elu+1, RoPE, planar scatter ----
    float* plain = (j0 < 256) ? g_qp : g_kp;
    float* roped = (j0 < 256) ? g_qr : g_kr;
    const int cb_base = (j0 & 255) + wn * 64;

#pragma unroll
    for (int fm = 0; fm < 2; fm++) {
        int t0 = wm * 32 + fm * 16 + gid;
        int wi0 = t0 & 63, wi1 = (t0 + 8) & 63;
#pragma unroll
        for (int fn = 0; fn < 8; fn++) {
            int cb = cb_base + fn * 8 + 2 * tig;
            int kidx = cb >> 1;
            float v0 = acc[fm][fn][0], v1 = acc[fm][fn][1];
            float v2 = acc[fm][fn][2], v3 = acc[fm][fn][3];
            float e0 = v0 > 0.f ? v0 + 1.f : __expf(v0);
            float e1 = v1 > 0.f ? v1 + 1.f : __expf(v1);
            float e2 = v2 > 0.f ? v2 + 1.f : __expf(v2);
            float e3 = v3 > 0.f ? v3 + 1.f : __expf(v3);
            float cs0 = g_cos[wi0 * 128 + kidx], sn0 = g_sin[wi0 * 128 + kidx];
            float cs1 = g_cos[wi1 * 128 + kidx], sn1 = g_sin[wi1 * 128 + kidx];
            size_t base = ((size_t)(bidx * CN + cb)) * NN + ntok + t0;
            plain[base]          = e0;
            plain[base + NN]     = e1;
            plain[base + 8]      = e2;
            plain[base + NN + 8] = e3;
            roped[base]          = cs0 * e0 - sn0 * e1;
            roped[base + NN]     = sn0 * e0 + cs0 * e1;
            roped[base + 8]      = cs1 * e2 - sn1 * e3;
            roped[base + NN + 8] = sn1 * e2 + cs1 * e3;
        }
    }
}

// ---------------- K4: k_mean over n ----------------
__global__ void k_kmean() {
    int warp = threadIdx.x / 32, lane = threadIdx.x % 32;
    int row = blockIdx.x * 8 + warp;
    const float* p = g_kp + (size_t)row * NN;
    float s = 0.f;
    for (int i = lane; i < NN / 4; i += 32) {
        float4 v = ((const float4*)p)[i];
        s += v.x + v.y + v.z + v.w;
    }
    for (int o = 16; o > 0; o >>= 1) s += __shfl_down_sync(~0u, s, o);
    if (lane == 0) g_kmean[row] = s * (1.f / 4096.f);
}

// ---------------- K5: z = 1 / (q . k_mean + 1e-6) ----------------
__global__ void k_z() {
    int bh = blockIdx.x;
    int b = bh / HEADS, h = bh % HEADS;
    __shared__ float km[64];
    int tid = threadIdx.x;
    if (tid < 64) km[tid] = g_kmean[b * CN + h * 64 + tid];
    __syncthreads();
    float acc[16];
#pragma unroll
    for (int i = 0; i < 16; i++) acc[i] = 0.f;
    for (int c = 0; c < 64; c++) {
        const float* row = g_qp + ((size_t)(b * CN + h * 64 + c)) * NN;
        float kmv = km[c];
#pragma unroll
        for (int i = 0; i < 16; i++) acc[i] = fmaf(row[tid + i * 256], kmv, acc[i]);
    }
    float* zp = g_z + (size_t)bh * NN;
#pragma unroll
    for (int i = 0; i < 16; i++) zp[tid + i * 256] = 1.f / (acc[i] + 1e-6f);
}

// ---------------- K6: kv = k_rope^T @ v / n ----------------
__global__ __launch_bounds__(256) void k_kv() {
    int bh = blockIdx.x;
    int chunk = blockIdx.y;
    int b = bh / HEADS, h = bh % HEADS;
    __shared__ float Ks[32][68];
    __shared__ float Vs[32][68];
    int tid = threadIdx.x;
    int ld_d = tid / 4;
    int ld_n8 = (tid % 4) * 8;
    int d0 = (tid / 16) * 4, e0 = (tid % 16) * 4;
    float kvacc[4][4];
#pragma unroll
    for (int i = 0; i < 4; i++)
#pragma unroll
        for (int j = 0; j < 4; j++) kvacc[i][j] = 0.f;

    int nstart = chunk * 1024;
    for (int it = 0; it < 32; it++) {
        int n0 = nstart + it * 32;
        const float* kp = g_kr + ((size_t)(b * CN + h * 64 + ld_d)) * NN + n0 + ld_n8;
        const float* vp = g_fused + ((size_t)(b * CN + h * 64 + ld_d)) * NN + n0 + ld_n8;
        float kvl[8], vvl[8];
        *(float4*)&kvl[0] = ((const float4*)kp)[0];
        *(float4*)&kvl[4] = ((const float4*)kp)[1];
        *(float4*)&vvl[0] = ((const float4*)vp)[0];
        *(float4*)&vvl[4] = ((const float4*)vp)[1];
        __syncthreads();
#pragma unroll
        for (int t = 0; t < 8; t++) {
            Ks[ld_n8 + t][ld_d] = kvl[t];
            Vs[ld_n8 + t][ld_d] = vvl[t];
        }
        __syncthreads();
#pragma unroll
        for (int nn = 0; nn < 32; nn++) {
            float kd[4], ve[4];
            *(float4*)kd = *(float4*)&Ks[nn][d0];
            *(float4*)ve = *(float4*)&Vs[nn][e0];
#pragma unroll
            for (int di = 0; di < 4; di++)
#pragma unroll
                for (int ei = 0; ei < 4; ei++)
                    kvacc[di][ei] = fmaf(kd[di], ve[ei], kvacc[di][ei]);
        }
    }
    const float scale = 1.f / 4096.f;
#pragma unroll
    for (int di = 0; di < 4; di++)
#pragma unroll
        for (int ei = 0; ei < 4; ei++)
            atomicAdd(&g_kv[((size_t)bh * 64 + d0 + di) * 64 + e0 + ei], kvacc[di][ei] * scale);
}

// ---------------- K7: lepe 3x3 dwconv on fused -> out ----------------
__global__ __launch_bounds__(256) void k_lepe(const float* __restrict__ w,
                                              const float* __restrict__ bias,
                                              float* __restrict__ out) {
    __shared__ float tile[72 * 72];
    __shared__ float wsm[9];
    const int c = blockIdx.x, b = blockIdx.y;
    const int tid = threadIdx.x;
    const size_t plane = ((size_t)(b * CN + c)) * NN;
    const float* xp = g_fused + plane;
    for (int i = tid; i < 72 * 72; i += 256) {
        int ty = i / 72, tx = i % 72;
        int gy = ty - 4, gx = tx - 4;
        float v = 0.f;
        if (gy >= 0 && gy < 64 && gx >= 0 && gx < 64) v = xp[gy * 64 + gx];
        tile[i] = v;
    }
    if (tid < 9) wsm[tid] = w[c * 9 + tid];
    __syncthreads();

    const float bv = bias[c];
    float* op = out + plane;
#pragma unroll
    for (int seg = 0; seg < 2; seg++) {
        int sidx = tid + seg * 256;
        int h = sidx / 8;
        int w0 = (sidx % 8) * 8;
        float acc[8];
#pragma unroll
        for (int j = 0; j < 8; j++) acc[j] = bv;
#pragma unroll
        for (int dy = 0; dy < 3; dy++) {
            const float* trow = &tile[(h + dy + 3) * 72 + (w0 + 3)];
            float rv[10];
#pragma unroll
            for (int xi = 0; xi < 10; xi++) rv[xi] = trow[xi];
#pragma unroll
            for (int dx = 0; dx < 3; dx++) {
                float wv = wsm[dy * 3 + dx];
#pragma unroll
                for (int j = 0; j < 8; j++) acc[j] = fmaf(rv[dx + j], wv, acc[j]);
            }
        }
        float4* o4 = (float4*)(op + h * 64 + w0);
        o4[0] = make_float4(acc[0], acc[1], acc[2], acc[3]);
        o4[1] = make_float4(acc[4], acc[5], acc[6], acc[7]);
    }
}

// ---------------- K8: out += z * (q_rope @ kv) ----------------
__global__ __launch_bounds__(256) void k_attn(float* __restrict__ out) {
    int bh = blockIdx.x;
    int nc = blockIdx.y;
    int b = bh / HEADS, h = bh % HEADS;
    __shared__ float KVs[64][64];
    __shared__ float Qs[64][64];
    __shared__ float zs[64];
    int tid = threadIdx.x;
    int n0 = nc * 64;
    {
        const float* kvp = g_kv + (size_t)bh * 4096;
#pragma unroll
        for (int i = 0; i < 4; i++) {
            int idx = tid * 16 + i * 4;
            *(float4*)&((float*)KVs)[idx] = *(const float4*)&kvp[idx];
        }
        int d = tid / 4, ns = (tid % 4) * 16;
        const float* qp = g_qr + ((size_t)(b * CN + h * 64 + d)) * NN + n0 + ns;
#pragma unroll
        for (int i = 0; i < 4; i++) *(float4*)&Qs[d][ns + i * 4] = ((const float4*)qp)[i];
        if (tid < 64) zs[tid] = g_z[(size_t)bh * NN + n0 + tid];
    }
    __syncthreads();

    int nl = tid / 4, e0 = (tid % 4) * 16;
    float acc[16];
#pragma unroll
    for (int i = 0; i < 16; i++) acc[i] = 0.f;
#pragma unroll
    for (int d = 0; d < 64; d++) {
        float qv = Qs[d][nl];
#pragma unroll
        for (int i = 0; i < 4; i++) {
            float4 kvv = *(float4*)&KVs[d][e0 + i * 4];
            acc[i * 4 + 0] = fmaf(qv, kvv.x, acc[i * 4 + 0]);
            acc[i * 4 + 1] = fmaf(qv, kvv.y, acc[i * 4 + 1]);
            acc[i * 4 + 2] = fmaf(qv, kvv.z, acc[i * 4 + 2]);
            acc[i * 4 + 3] = fmaf(qv, kvv.w, acc[i * 4 + 3]);
        }
    }
    float zv = zs[nl];
    int n = n0 + nl;
#pragma unroll
    for (int ei = 0; ei < 16; ei++) {
        size_t off = ((size_t)(b * CN + h * 64 + e0 + ei)) * NN + n;
        out[off] += acc[ei] * zv;
    }
}

// ---------------- launch ----------------
extern "C" void kernel_launch(void* const* d_in, const int* in_sizes, int n_in,
                              void* d_out, int out_size) {
    const float* x   = (const float*)d_in[0];
    const float* cw0 = (const float*)d_in[1];
    const float* cb0 = (const float*)d_in[2];
    const float* cw1 = (const float*)d_in[3];
    const float* cb1 = (const float*)d_in[4];
    const float* cw2 = (const float*)d_in[5];
    const float* cb2 = (const float*)d_in[6];
    const float* cw3 = (const float*)d_in[7];
    const float* cb3 = (const float*)d_in[8];
    const float* gn_w = (const float*)d_in[9];
    const float* gn_b = (const float*)d_in[10];
    const float* fw   = (const float*)d_in[11];
    const float* qkw  = (const float*)d_in[12];
    const float* lepe_w = (const float*)d_in[13];
    const float* lepe_b = (const float*)d_in[14];
    float* out = (float*)d_out;

    static bool attr_set = false;
    const int GEMM_SMEM = 2 * 256 * GPITCH * 2;   // 139264 bytes
    if (!attr_set) {
        cudaFuncSetAttribute(k_gemm_tc, cudaFuncAttributeMaxDynamicSharedMemorySize, GEMM_SMEM);
        attr_set = true;
    }

    k_init<<<1024, 256>>>(fw);
    k_wtrans<<<512, 256>>>(qkw);

    dim3 gconv(CN, BN);
    k_conv4<<<gconv, 256>>>(x, cw0, cb0, cw1, cb1, cw2, cb2, cw3, cb3);

    k_fuse<<<BN * CN * NN / 8 / 256, 256>>>(gn_w, gn_b);

    dim3 ggemm(512, 4);
    k_gemm_tc<<<ggemm, 256, GEMM_SMEM>>>();

    k_kmean<<<BN * CN / 8, 256>>>();
    k_z<<<BN * HEADS, 256>>>();

    dim3 gkv(BN * HEADS, 4);
    k_kv<<<gkv, 256>>>();

    k_lepe<<<gconv, 256>>>(lepe_w, lepe_b, out);

    dim3 gattn(BN * HEADS, NN / 64);
    k_attn<<<gattn, 256>>>(out);
}

// round 13
// speedup vs baseline: 1.0007x; 1.0007x over previous
#include <cuda_runtime.h>
#include <cuda_fp16.h>
#include <math.h>

#define BN 16
#define CN 256
#define NN 4096          // H*W
#define HEADS 4
#define HD 64
#define GROUPS 4

// ---------------- scratch (__device__ globals: allocation-free) ----------------
__device__ __align__(128) __half g_convh[4][BN * CN * NN]; // conv outputs fp16
__device__ float g_fused[BN * CN * NN];     // fused (fp32, v path)
__device__ __align__(128) __half g_fa[BN * CN * NN];       // fused fp16 (GEMM A)
__device__ __align__(128) __half g_wth[256 * 512];         // qk_w^T fp16: [k][j]
__device__ float g_qp[BN * CN * NN];
__device__ float g_kp[BN * CN * NN];
__device__ float g_qr[BN * CN * NN];
__device__ float g_kr[BN * CN * NN];
__device__ float g_kmean[BN * CN];
__device__ float g_z[BN * HEADS * NN];
__device__ float g_kv[BN * HEADS * HD * HD];
__device__ float g_cos[64 * 128];
__device__ float g_sin[64 * 128];
__device__ float g_fw[4];
__device__ float g_ssum[4 * BN * GROUPS];
__device__ float g_ssq[4 * BN * GROUPS];

// ---------------- K0: init ----------------
__global__ void k_init(const float* __restrict__ fusion_w) {
    int idx = blockIdx.x * 256 + threadIdx.x;
    if (idx < BN * HEADS * HD * HD) g_kv[idx] = 0.f;
    if (idx < 4 * BN * GROUPS) { g_ssum[idx] = 0.f; g_ssq[idx] = 0.f; }
    if (idx < 64 * 128) {
        int w = idx / 128, k = idx % 128;
        float theta = powf(10000.f, -(float)k / 128.f);
        float ang = (float)w * theta;
        g_cos[idx] = cosf(ang);
        g_sin[idx] = sinf(ang);
    }
    if (idx == 0) {
        float m = fusion_w[0];
        for (int i = 1; i < 4; i++) m = fmaxf(m, fusion_w[i]);
        float e[4], s = 0.f;
        for (int i = 0; i < 4; i++) { e[i] = expf(fusion_w[i] - m); s += e[i]; }
        for (int i = 0; i < 4; i++) g_fw[i] = e[i] / s;
    }
}

// ---------------- transpose qk_w [512,256] -> g_wth [256][512] fp16 ----------------
__global__ void k_wtrans(const float* __restrict__ qkw) {
    int id = blockIdx.x * 256 + threadIdx.x;   // 512*256 total
    int k = id / 512, j = id % 512;
    g_wth[id] = __float2half(qkw[j * 256 + k]);
}

// ---------------- K1: all 4 depthwise convs fused, one tile load ----------------
__global__ __launch_bounds__(256) void k_conv4(
    const float* __restrict__ x,
    const float* __restrict__ w3, const float* __restrict__ b3,
    const float* __restrict__ w5, const float* __restrict__ b5,
    const float* __restrict__ w7, const float* __restrict__ b7,
    const float* __restrict__ w9, const float* __restrict__ b9) {
    __shared__ float tile[72 * 72];
    __shared__ float ws3[9], ws5[25], ws7[49], ws9[81];
    __shared__ float rsum[4][8], rsq[4][8];
    const int c = blockIdx.x, b = blockIdx.y;
    const int tid = threadIdx.x;
    const size_t plane = ((size_t)(b * CN + c)) * NN;
    const float* xp = x + plane;
    for (int i = tid; i < 72 * 72; i += 256) {
        int ty = i / 72, tx = i % 72;
        int gy = ty - 4, gx = tx - 4;
        float v = 0.f;
        if (gy >= 0 && gy < 64 && gx >= 0 && gx < 64) v = xp[gy * 64 + gx];
        tile[i] = v;
    }
    if (tid < 9)  ws3[tid] = w3[c * 9 + tid];
    if (tid < 25) ws5[tid] = w5[c * 25 + tid];
    if (tid < 49) ws7[tid] = w7[c * 49 + tid];
    if (tid < 81) ws9[tid] = w9[c * 81 + tid];
    __syncthreads();

    const float bv[4] = {b3[c], b5[c], b7[c], b9[c]};
    float s[4] = {0.f, 0.f, 0.f, 0.f}, q[4] = {0.f, 0.f, 0.f, 0.f};

#pragma unroll
    for (int seg = 0; seg < 2; seg++) {
        int sidx = tid + seg * 256;
        int h = sidx / 8;
        int w0 = (sidx % 8) * 8;
        float a[4][8];
#pragma unroll
        for (int br = 0; br < 4; br++)
#pragma unroll
            for (int j = 0; j < 8; j++) a[br][j] = bv[br];

#pragma unroll
        for (int dy = 0; dy < 9; dy++) {
            const float* trow = &tile[(h + dy) * 72 + w0];
            float rv[16];
#pragma unroll
            for (int xi = 0; xi < 16; xi++) rv[xi] = trow[xi];
            // k9 (pad 4): rows 0..8, cols rv[dx + j]
#pragma unroll
            for (int dx = 0; dx < 9; dx++) {
                float wv = ws9[dy * 9 + dx];
#pragma unroll
                for (int j = 0; j < 8; j++) a[3][j] = fmaf(rv[dx + j], wv, a[3][j]);
            }
            if (dy >= 1 && dy <= 7) {   // k7
                int d7 = dy - 1;
#pragma unroll
                for (int dx = 0; dx < 7; dx++) {
                    float wv = ws7[d7 * 7 + dx];
#pragma unroll
                    for (int j = 0; j < 8; j++) a[2][j] = fmaf(rv[dx + 1 + j], wv, a[2][j]);
                }
            }
            if (dy >= 2 && dy <= 6) {   // k5
                int d5 = dy - 2;
#pragma unroll
                for (int dx = 0; dx < 5; dx++) {
                    float wv = ws5[d5 * 5 + dx];
#pragma unroll
                    for (int j = 0; j < 8; j++) a[1][j] = fmaf(rv[dx + 2 + j], wv, a[1][j]);
                }
            }
            if (dy >= 3 && dy <= 5) {   // k3
                int d3 = dy - 3;
#pragma unroll
                for (int dx = 0; dx < 3; dx++) {
                    float wv = ws3[d3 * 3 + dx];
#pragma unroll
                    for (int j = 0; j < 8; j++) a[0][j] = fmaf(rv[dx + 3 + j], wv, a[0][j]);
                }
            }
        }

#pragma unroll
        for (int br = 0; br < 4; br++) {
            __half2 hh[4];
#pragma unroll
            for (int t = 0; t < 4; t++) hh[t] = __floats2half2_rn(a[br][2 * t], a[br][2 * t + 1]);
            *(uint4*)(&g_convh[br][plane + h * 64 + w0]) = *(uint4*)hh;
#pragma unroll
            for (int j = 0; j < 8; j++) { s[br] += a[br][j]; q[br] = fmaf(a[br][j], a[br][j], q[br]); }
        }
    }

    int warp = tid / 32, lane = tid % 32;
#pragma unroll
    for (int br = 0; br < 4; br++) {
        float ss = s[br], qq = q[br];
        for (int o = 16; o > 0; o >>= 1) {
            ss += __shfl_down_sync(~0u, ss, o);
            qq += __shfl_down_sync(~0u, qq, o);
        }
        if (lane == 0) { rsum[br][warp] = ss; rsq[br][warp] = qq; }
    }
    __syncthreads();
    if (tid < 4) {
        float ts = 0.f, tq = 0.f;
        for (int i = 0; i < 8; i++) { ts += rsum[tid][i]; tq += rsq[tid][i]; }
        int g = c >> 6;
        atomicAdd(&g_ssum[(tid * BN + b) * GROUPS + g], ts);
        atomicAdd(&g_ssq [(tid * BN + b) * GROUPS + g], tq);
    }
}

// ---------------- K2: groupnorm + sigmoid + weighted fuse (fp16 in, fp32+fp16 out) ----------------
__global__ void k_fuse(const float* __restrict__ gn_w, const float* __restrict__ gn_b) {
    int idx8 = blockIdx.x * 256 + threadIdx.x;   // uint4-of-halfs index (8 elems)
    int base = idx8 * 8;
    int b = base / (CN * NN);
    int c = (base / NN) % CN;
    int g = c >> 6;
    const float cnt = 64.f * 4096.f;
    float res[8];
#pragma unroll
    for (int t = 0; t < 8; t++) res[t] = 0.f;
#pragma unroll
    for (int br = 0; br < 4; br++) {
        float sS  = g_ssum[(br * BN + b) * GROUPS + g];
        float sq = g_ssq [(br * BN + b) * GROUPS + g];
        float mean = sS / cnt;
        float var = sq / cnt - mean * mean;
        float rstd = rsqrtf(var + 1e-5f);
        float gamma = gn_w[br * CN + c] * rstd;
        float beta = gn_b[br * CN + c] - mean * gamma;
        float wt = g_fw[br];
        uint4 raw = *(const uint4*)(&g_convh[br][base]);
        const __half2* h2 = (const __half2*)&raw;
#pragma unroll
        for (int t = 0; t < 4; t++) {
            float2 f = __half22float2(h2[t]);
            res[2 * t]     += wt / (1.f + __expf(-(f.x * gamma + beta)));
            res[2 * t + 1] += wt / (1.f + __expf(-(f.y * gamma + beta)));
        }
    }
    *(float4*)(g_fused + base)     = make_float4(res[0], res[1], res[2], res[3]);
    *(float4*)(g_fused + base + 4) = make_float4(res[4], res[5], res[6], res[7]);
    __half2 hh[4];
#pragma unroll
    for (int t = 0; t < 4; t++) hh[t] = __floats2half2_rn(res[2 * t], res[2 * t + 1]);
    *(uint4*)(&g_fa[base]) = *(uint4*)hh;
}

// ---------------- tensor-core helpers ----------------
__device__ __forceinline__ unsigned s2u(const void* p) {
    return (unsigned)__cvta_generic_to_shared(p);
}
__device__ __forceinline__ void cpa16(unsigned dst, const void* src) {
    asm volatile("cp.async.cg.shared.global [%0], [%1], 16;" :: "r"(dst), "l"(src));
}
__device__ __forceinline__ void cpcommit() {
    asm volatile("cp.async.commit_group;");
}
template <int N>
__device__ __forceinline__ void cpwait() {
    asm volatile("cp.async.wait_group %0;" :: "n"(N));
}
__device__ __forceinline__ void ldsm4t(unsigned* r, unsigned addr) {
    asm volatile("ldmatrix.sync.aligned.m8n8.x4.trans.shared.b16 {%0,%1,%2,%3}, [%4];"
        : "=r"(r[0]), "=r"(r[1]), "=r"(r[2]), "=r"(r[3]) : "r"(addr));
}
__device__ __forceinline__ void mma16816(float* c, const unsigned* a, const unsigned* b) {
    asm volatile(
        "mma.sync.aligned.m16n8k16.row.col.f32.f16.f16.f32 "
        "{%0,%1,%2,%3}, {%4,%5,%6,%7}, {%8,%9}, {%0,%1,%2,%3};"
        : "+f"(c[0]), "+f"(c[1]), "+f"(c[2]), "+f"(c[3])
        : "r"(a[0]), "r"(a[1]), "r"(a[2]), "r"(a[3]), "r"(b[0]), "r"(b[1]));
}

// ---------------- K3: QK GEMM fp16 mma + elu + RoPE epilogue ----------------
// block 128(m tokens) x 128(n chans), full K=256 resident in smem, cp.async staged.
#define GPITCH 136   // halfs per smem row (128 + 8 pad)
__global__ __launch_bounds__(256) void k_gemm_tc(void) {
    extern __shared__ __align__(16) __half sm[];
    __half* As = sm;                 // [256 k][GPITCH m]
    __half* Bs = sm + 256 * GPITCH;  // [256 k][GPITCH j]

    const int tid = threadIdx.x;
    const int warp = tid >> 5;
    const int lane = tid & 31;
    const int gid = lane >> 2, tig = lane & 3;
    const int wm = warp & 3;     // 4 m-tiles of 32
    const int wn = warp >> 2;    // 2 n-tiles of 64

    const int m0 = blockIdx.x * 128;
    const int j0 = blockIdx.y * 128;
    const int bidx = m0 / NN;
    const int ntok = m0 % NN;

    // ---- issue all loads: 8 groups of K=32 rows each (A + B) ----
    const unsigned sA = s2u(As), sB = s2u(Bs);
    const __half* srcA = g_fa + (size_t)bidx * CN * NN + ntok;
#pragma unroll
    for (int g = 0; g < 8; g++) {
#pragma unroll
        for (int rep = 0; rep < 2; rep++) {
            int cidx = tid + rep * 256;          // 0..511
            int kl = g * 32 + (cidx >> 4);
            int off = (cidx & 15) * 8;
            cpa16(sA + (kl * GPITCH + off) * 2, srcA + (size_t)kl * NN + off);
            cpa16(sB + (kl * GPITCH + off) * 2, g_wth + kl * 512 + j0 + off);
        }
        cpcommit();
    }

    // ---- ldmatrix address precompute ----
    const int l8 = lane >> 3, r8 = lane & 7;
    const int a_kr = r8 + ((l8 >> 1) << 3);
    const int a_mc = (l8 & 1) << 3;
    const int b_kr = r8 + ((l8 & 1) << 3);
    const int b_nc = (l8 >> 1) << 3;
    unsigned aaddr[2], baddr[4];
#pragma unroll
    for (int fm = 0; fm < 2; fm++)
        aaddr[fm] = sA + (a_kr * GPITCH + wm * 32 + fm * 16 + a_mc) * 2;
#pragma unroll
    for (int p = 0; p < 4; p++)
        baddr[p] = sB + (b_kr * GPITCH + wn * 64 + p * 16 + b_nc) * 2;

    float acc[2][8][4];
#pragma unroll
    for (int fm = 0; fm < 2; fm++)
#pragma unroll
        for (int fn = 0; fn < 8; fn++)
#pragma unroll
            for (int t = 0; t < 4; t++) acc[fm][fn][t] = 0.f;

    // ---- staged compute: wait group kt, compute its two k16 slices ----
#pragma unroll
    for (int kt = 0; kt < 8; kt++) {
        switch (kt) {
            case 0: cpwait<7>(); break; case 1: cpwait<6>(); break;
            case 2: cpwait<5>(); break; case 3: cpwait<4>(); break;
            case 4: cpwait<3>(); break; case 5: cpwait<2>(); break;
            case 6: cpwait<1>(); break; default: cpwait<0>(); break;
        }
        __syncthreads();
#pragma unroll
        for (int h16 = 0; h16 < 2; h16++) {
            const unsigned koff = (unsigned)(kt * 32 + h16 * 16) * (GPITCH * 2);
            unsigned a[2][4], b[8][2];
            ldsm4t(a[0], aaddr[0] + koff);
            ldsm4t(a[1], aaddr[1] + koff);
#pragma unroll
            for (int p = 0; p < 4; p++) {
                unsigned t[4];
                ldsm4t(t, baddr[p] + koff);
                b[2 * p][0] = t[0]; b[2 * p][1] = t[1];
                b[2 * p + 1][0] = t[2]; b[2 * p + 1][1] = t[3];
            }
#pragma unroll
            for (int fm = 0; fm < 2; fm++)
#pragma unroll
                for (int fn = 0; fn < 8; fn++)
                    mma16816(acc[fm][fn], a[fm], b[fn]);
        }
    }

    // ---- epilogue: elu+1, RoPE, planar scatter ----
    float* plain = (j0 < 256) ? g_qp : g_kp;
    float* roped = (j0 < 256) ? g_qr : g_kr;
    const int cb_base = (j0 & 255) + wn * 64;

#pragma unroll
    for (int fm = 0; fm < 2; fm++) {
        int t0 = wm * 32 + fm * 16 + gid;
        int wi0 = t0 & 63, wi1 = (t0 + 8) & 63;
#pragma unroll
        for (int fn = 0; fn < 8; fn++) {
            int cb = cb_base + fn * 8 + 2 * tig;
            int kidx = cb >> 1;
            float v0 = acc[fm][fn][0], v1 = acc[fm][fn][1];
            float v2 = acc[fm][fn][2], v3 = acc[fm][fn][3];
            float e0 = v0 > 0.f ? v0 + 1.f : __expf(v0);
            float e1 = v1 > 0.f ? v1 + 1.f : __expf(v1);
            float e2 = v2 > 0.f ? v2 + 1.f : __expf(v2);
            float e3 = v3 > 0.f ? v3 + 1.f : __expf(v3);
            float cs0 = g_cos[wi0 * 128 + kidx], sn0 = g_sin[wi0 * 128 + kidx];
            float cs1 = g_cos[wi1 * 128 + kidx], sn1 = g_sin[wi1 * 128 + kidx];
            size_t base = ((size_t)(bidx * CN + cb)) * NN + ntok + t0;
            plain[base]          = e0;
            plain[base + NN]     = e1;
            plain[base + 8]      = e2;
            plain[base + NN + 8] = e3;
            roped[base]          = cs0 * e0 - sn0 * e1;
            roped[base + NN]     = sn0 * e0 + cs0 * e1;
            roped[base + 8]      = cs1 * e2 - sn1 * e3;
            roped[base + NN + 8] = sn1 * e2 + cs1 * e3;
        }
    }
}

// ---------------- K4: k_mean over n ----------------
__global__ void k_kmean() {
    int warp = threadIdx.x / 32, lane = threadIdx.x % 32;
    int row = blockIdx.x * 8 + warp;
    const float* p = g_kp + (size_t)row * NN;
    float s = 0.f;
    for (int i = lane; i < NN / 4; i += 32) {
        float4 v = ((const float4*)p)[i];
        s += v.x + v.y + v.z + v.w;
    }
    for (int o = 16; o > 0; o >>= 1) s += __shfl_down_sync(~0u, s, o);
    if (lane == 0) g_kmean[row] = s * (1.f / 4096.f);
}

// ---------------- K5: z = 1 / (q . k_mean + 1e-6) ----------------
__global__ void k_z() {
    int bh = blockIdx.x;
    int b = bh / HEADS, h = bh % HEADS;
    __shared__ float km[64];
    int tid = threadIdx.x;
    if (tid < 64) km[tid] = g_kmean[b * CN + h * 64 + tid];
    __syncthreads();
    float acc[16];
#pragma unroll
    for (int i = 0; i < 16; i++) acc[i] = 0.f;
    for (int c = 0; c < 64; c++) {
        const float* row = g_qp + ((size_t)(b * CN + h * 64 + c)) * NN;
        float kmv = km[c];
#pragma unroll
        for (int i = 0; i < 16; i++) acc[i] = fmaf(row[tid + i * 256], kmv, acc[i]);
    }
    float* zp = g_z + (size_t)bh * NN;
#pragma unroll
    for (int i = 0; i < 16; i++) zp[tid + i * 256] = 1.f / (acc[i] + 1e-6f);
}

// ---------------- K6: kv = k_rope^T @ v / n ----------------
__global__ __launch_bounds__(256) void k_kv() {
    int bh = blockIdx.x;
    int chunk = blockIdx.y;
    int b = bh / HEADS, h = bh % HEADS;
    __shared__ float Ks[32][68];
    __shared__ float Vs[32][68];
    int tid = threadIdx.x;
    int ld_d = tid / 4;
    int ld_n8 = (tid % 4) * 8;
    int d0 = (tid / 16) * 4, e0 = (tid % 16) * 4;
    float kvacc[4][4];
#pragma unroll
    for (int i = 0; i < 4; i++)
#pragma unroll
        for (int j = 0; j < 4; j++) kvacc[i][j] = 0.f;

    int nstart = chunk * 1024;
    for (int it = 0; it < 32; it++) {
        int n0 = nstart + it * 32;
        const float* kp = g_kr + ((size_t)(b * CN + h * 64 + ld_d)) * NN + n0 + ld_n8;
        const float* vp = g_fused + ((size_t)(b * CN + h * 64 + ld_d)) * NN + n0 + ld_n8;
        float kvl[8], vvl[8];
        *(float4*)&kvl[0] = ((const float4*)kp)[0];
        *(float4*)&kvl[4] = ((const float4*)kp)[1];
        *(float4*)&vvl[0] = ((const float4*)vp)[0];
        *(float4*)&vvl[4] = ((const float4*)vp)[1];
        __syncthreads();
#pragma unroll
        for (int t = 0; t < 8; t++) {
            Ks[ld_n8 + t][ld_d] = kvl[t];
            Vs[ld_n8 + t][ld_d] = vvl[t];
        }
        __syncthreads();
#pragma unroll
        for (int nn = 0; nn < 32; nn++) {
            float kd[4], ve[4];
            *(float4*)kd = *(float4*)&Ks[nn][d0];
            *(float4*)ve = *(float4*)&Vs[nn][e0];
#pragma unroll
            for (int di = 0; di < 4; di++)
#pragma unroll
                for (int ei = 0; ei < 4; ei++)
                    kvacc[di][ei] = fmaf(kd[di], ve[ei], kvacc[di][ei]);
        }
    }
    const float scale = 1.f / 4096.f;
#pragma unroll
    for (int di = 0; di < 4; di++)
#pragma unroll
        for (int ei = 0; ei < 4; ei++)
            atomicAdd(&g_kv[((size_t)bh * 64 + d0 + di) * 64 + e0 + ei], kvacc[di][ei] * scale);
}

// ---------------- K7: lepe 3x3 dwconv on fused -> out ----------------
__global__ __launch_bounds__(256) void k_lepe(const float* __restrict__ w,
                                              const float* __restrict__ bias,
                                              float* __restrict__ out) {
    __shared__ float tile[72 * 72];
    __shared__ float wsm[9];
    const int c = blockIdx.x, b = blockIdx.y;
    const int tid = threadIdx.x;
    const size_t plane = ((size_t)(b * CN + c)) * NN;
    const float* xp = g_fused + plane;
    for (int i = tid; i < 72 * 72; i += 256) {
        int ty = i / 72, tx = i % 72;
        int gy = ty - 4, gx = tx - 4;
        float v = 0.f;
        if (gy >= 0 && gy < 64 && gx >= 0 && gx < 64) v = xp[gy * 64 + gx];
        tile[i] = v;
    }
    if (tid < 9) wsm[tid] = w[c * 9 + tid];
    __syncthreads();

    const float bv = bias[c];
    float* op = out + plane;
#pragma unroll
    for (int seg = 0; seg < 2; seg++) {
        int sidx = tid + seg * 256;
        int h = sidx / 8;
        int w0 = (sidx % 8) * 8;
        float acc[8];
#pragma unroll
        for (int j = 0; j < 8; j++) acc[j] = bv;
#pragma unroll
        for (int dy = 0; dy < 3; dy++) {
            const float* trow = &tile[(h + dy + 3) * 72 + (w0 + 3)];
            float rv[10];
#pragma unroll
            for (int xi = 0; xi < 10; xi++) rv[xi] = trow[xi];
#pragma unroll
            for (int dx = 0; dx < 3; dx++) {
                float wv = wsm[dy * 3 + dx];
#pragma unroll
                for (int j = 0; j < 8; j++) acc[j] = fmaf(rv[dx + j], wv, acc[j]);
            }
        }
        float4* o4 = (float4*)(op + h * 64 + w0);
        o4[0] = make_float4(acc[0], acc[1], acc[2], acc[3]);
        o4[1] = make_float4(acc[4], acc[5], acc[6], acc[7]);
    }
}

// ---------------- K8: out += z * (q_rope @ kv) ----------------
__global__ __launch_bounds__(256) void k_attn(float* __restrict__ out) {
    int bh = blockIdx.x;
    int nc = blockIdx.y;
    int b = bh / HEADS, h = bh % HEADS;
    __shared__ float KVs[64][64];
    __shared__ float Qs[64][64];
    __shared__ float zs[64];
    int tid = threadIdx.x;
    int n0 = nc * 64;
    {
        const float* kvp = g_kv + (size_t)bh * 4096;
#pragma unroll
        for (int i = 0; i < 4; i++) {
            int idx = tid * 16 + i * 4;
            *(float4*)&((float*)KVs)[idx] = *(const float4*)&kvp[idx];
        }
        int d = tid / 4, ns = (tid % 4) * 16;
        const float* qp = g_qr + ((size_t)(b * CN + h * 64 + d)) * NN + n0 + ns;
#pragma unroll
        for (int i = 0; i < 4; i++) *(float4*)&Qs[d][ns + i * 4] = ((const float4*)qp)[i];
        if (tid < 64) zs[tid] = g_z[(size_t)bh * NN + n0 + tid];
    }
    __syncthreads();

    int nl = tid / 4, e0 = (tid % 4) * 16;
    float acc[16];
#pragma unroll
    for (int i = 0; i < 16; i++) acc[i] = 0.f;
#pragma unroll
    for (int d = 0; d < 64; d++) {
        float qv = Qs[d][nl];
#pragma unroll
        for (int i = 0; i < 4; i++) {
            float4 kvv = *(float4*)&KVs[d][e0 + i * 4];
            acc[i * 4 + 0] = fmaf(qv, kvv.x, acc[i * 4 + 0]);
            acc[i * 4 + 1] = fmaf(qv, kvv.y, acc[i * 4 + 1]);
            acc[i * 4 + 2] = fmaf(qv, kvv.z, acc[i * 4 + 2]);
            acc[i * 4 + 3] = fmaf(qv, kvv.w, acc[i * 4 + 3]);
        }
    }
    float zv = zs[nl];
    int n = n0 + nl;
#pragma unroll
    for (int ei = 0; ei < 16; ei++) {
        size_t off = ((size_t)(b * CN + h * 64 + e0 + ei)) * NN + n;
        out[off] += acc[ei] * zv;
    }
}

// ---------------- launch ----------------
extern "C" void kernel_launch(void* const* d_in, const int* in_sizes, int n_in,
                              void* d_out, int out_size) {
    const float* x   = (const float*)d_in[0];
    const float* cw0 = (const float*)d_in[1];
    const float* cb0 = (const float*)d_in[2];
    const float* cw1 = (const float*)d_in[3];
    const float* cb1 = (const float*)d_in[4];
    const float* cw2 = (const float*)d_in[5];
    const float* cb2 = (const float*)d_in[6];
    const float* cw3 = (const float*)d_in[7];
    const float* cb3 = (const float*)d_in[8];
    const float* gn_w = (const float*)d_in[9];
    const float* gn_b = (const float*)d_in[10];
    const float* fw   = (const float*)d_in[11];
    const float* qkw  = (const float*)d_in[12];
    const float* lepe_w = (const float*)d_in[13];
    const float* lepe_b = (const float*)d_in[14];
    float* out = (float*)d_out;

    static bool attr_set = false;
    const int GEMM_SMEM = 2 * 256 * GPITCH * 2;   // 139264 bytes
    if (!attr_set) {
        cudaFuncSetAttribute(k_gemm_tc, cudaFuncAttributeMaxDynamicSharedMemorySize, GEMM_SMEM);
        attr_set = true;
    }

    k_init<<<1024, 256>>>(fw);
    k_wtrans<<<512, 256>>>(qkw);

    dim3 gconv(CN, BN);
    k_conv4<<<gconv, 256>>>(x, cw0, cb0, cw1, cb1, cw2, cb2, cw3, cb3);

    k_fuse<<<BN * CN * NN / 8 / 256, 256>>>(gn_w, gn_b);

    dim3 ggemm(512, 4);
    k_gemm_tc<<<ggemm, 256, GEMM_SMEM>>>();

    k_kmean<<<BN * CN / 8, 256>>>();
    k_z<<<BN * HEADS, 256>>>();

    dim3 gkv(BN * HEADS, 4);
    k_kv<<<gkv, 256>>>();

    k_lepe<<<gconv, 256>>>(lepe_w, lepe_b, out);

    dim3 gattn(BN * HEADS, NN / 64);
    k_attn<<<gattn, 256>>>(out);
}

// round 14
// speedup vs baseline: 1.0010x; 1.0002x over previous
#include <cuda_runtime.h>
#include <cuda_fp16.h>
#include <math.h>

#define BN 16
#define CN 256
#define NN 4096          // H*W
#define HEADS 4
#define HD 64
#define GROUPS 4

// ---------------- scratch (__device__ globals: allocation-free) ----------------
__device__ __align__(128) __half g_convh[4][BN * CN * NN]; // conv outputs fp16
__device__ float g_fused[BN * CN * NN];     // fused (fp32, v path)
__device__ __align__(128) __half g_fa[BN * CN * NN];       // fused fp16 (GEMM A)
__device__ __align__(128) __half g_wth[256 * 512];         // qk_w^T fp16: [k][j]
__device__ float g_qp[BN * CN * NN];
__device__ float g_kp[BN * CN * NN];
__device__ float g_qr[BN * CN * NN];
__device__ float g_kr[BN * CN * NN];
__device__ float g_kmean[BN * CN];
__device__ float g_z[BN * HEADS * NN];
__device__ float g_kv[BN * HEADS * HD * HD];
__device__ float g_cos[64 * 128];
__device__ float g_sin[64 * 128];
__device__ float g_fw[4];
__device__ float g_ssum[4 * BN * GROUPS];
__device__ float g_ssq[4 * BN * GROUPS];

// ---------------- K0: init ----------------
__global__ void k_init(const float* __restrict__ fusion_w) {
    int idx = blockIdx.x * 256 + threadIdx.x;
    if (idx < BN * HEADS * HD * HD) g_kv[idx] = 0.f;
    if (idx < 4 * BN * GROUPS) { g_ssum[idx] = 0.f; g_ssq[idx] = 0.f; }
    if (idx < 64 * 128) {
        int w = idx / 128, k = idx % 128;
        float theta = powf(10000.f, -(float)k / 128.f);
        float ang = (float)w * theta;
        g_cos[idx] = cosf(ang);
        g_sin[idx] = sinf(ang);
    }
    if (idx == 0) {
        float m = fusion_w[0];
        for (int i = 1; i < 4; i++) m = fmaxf(m, fusion_w[i]);
        float e[4], s = 0.f;
        for (int i = 0; i < 4; i++) { e[i] = expf(fusion_w[i] - m); s += e[i]; }
        for (int i = 0; i < 4; i++) g_fw[i] = e[i] / s;
    }
}

// ---------------- transpose qk_w [512,256] -> g_wth [256][512] fp16 ----------------
__global__ void k_wtrans(const float* __restrict__ qkw) {
    int id = blockIdx.x * 256 + threadIdx.x;   // 512*256 total
    int k = id / 512, j = id % 512;
    g_wth[id] = __float2half(qkw[j * 256 + k]);
}

// ---------------- K1: all 4 depthwise convs fused, one tile load ----------------
__global__ __launch_bounds__(256) void k_conv4(
    const float* __restrict__ x,
    const float* __restrict__ w3, const float* __restrict__ b3,
    const float* __restrict__ w5, const float* __restrict__ b5,
    const float* __restrict__ w7, const float* __restrict__ b7,
    const float* __restrict__ w9, const float* __restrict__ b9) {
    __shared__ float tile[72 * 72];
    __shared__ float ws3[9], ws5[25], ws7[49], ws9[81];
    __shared__ float rsum[4][8], rsq[4][8];
    const int c = blockIdx.x, b = blockIdx.y;
    const int tid = threadIdx.x;
    const size_t plane = ((size_t)(b * CN + c)) * NN;
    const float* xp = x + plane;
    for (int i = tid; i < 72 * 72; i += 256) {
        int ty = i / 72, tx = i % 72;
        int gy = ty - 4, gx = tx - 4;
        float v = 0.f;
        if (gy >= 0 && gy < 64 && gx >= 0 && gx < 64) v = xp[gy * 64 + gx];
        tile[i] = v;
    }
    if (tid < 9)  ws3[tid] = w3[c * 9 + tid];
    if (tid < 25) ws5[tid] = w5[c * 25 + tid];
    if (tid < 49) ws7[tid] = w7[c * 49 + tid];
    if (tid < 81) ws9[tid] = w9[c * 81 + tid];
    __syncthreads();

    const float bv[4] = {b3[c], b5[c], b7[c], b9[c]};
    float s[4] = {0.f, 0.f, 0.f, 0.f}, q[4] = {0.f, 0.f, 0.f, 0.f};

#pragma unroll
    for (int seg = 0; seg < 2; seg++) {
        int sidx = tid + seg * 256;
        int h = sidx / 8;
        int w0 = (sidx % 8) * 8;
        float a[4][8];
#pragma unroll
        for (int br = 0; br < 4; br++)
#pragma unroll
            for (int j = 0; j < 8; j++) a[br][j] = bv[br];

#pragma unroll
        for (int dy = 0; dy < 9; dy++) {
            const float* trow = &tile[(h + dy) * 72 + w0];
            float rv[16];
#pragma unroll
            for (int xi = 0; xi < 16; xi++) rv[xi] = trow[xi];
            // k9 (pad 4): rows 0..8, cols rv[dx + j]
#pragma unroll
            for (int dx = 0; dx < 9; dx++) {
                float wv = ws9[dy * 9 + dx];
#pragma unroll
                for (int j = 0; j < 8; j++) a[3][j] = fmaf(rv[dx + j], wv, a[3][j]);
            }
            if (dy >= 1 && dy <= 7) {   // k7
                int d7 = dy - 1;
#pragma unroll
                for (int dx = 0; dx < 7; dx++) {
                    float wv = ws7[d7 * 7 + dx];
#pragma unroll
                    for (int j = 0; j < 8; j++) a[2][j] = fmaf(rv[dx + 1 + j], wv, a[2][j]);
                }
            }
            if (dy >= 2 && dy <= 6) {   // k5
                int d5 = dy - 2;
#pragma unroll
                for (int dx = 0; dx < 5; dx++) {
                    float wv = ws5[d5 * 5 + dx];
#pragma unroll
                    for (int j = 0; j < 8; j++) a[1][j] = fmaf(rv[dx + 2 + j], wv, a[1][j]);
                }
            }
            if (dy >= 3 && dy <= 5) {   // k3
                int d3 = dy - 3;
#pragma unroll
                for (int dx = 0; dx < 3; dx++) {
                    float wv = ws3[d3 * 3 + dx];
#pragma unroll
                    for (int j = 0; j < 8; j++) a[0][j] = fmaf(rv[dx + 3 + j], wv, a[0][j]);
                }
            }
        }

#pragma unroll
        for (int br = 0; br < 4; br++) {
            __half2 hh[4];
#pragma unroll
            for (int t = 0; t < 4; t++) hh[t] = __floats2half2_rn(a[br][2 * t], a[br][2 * t + 1]);
            *(uint4*)(&g_convh[br][plane + h * 64 + w0]) = *(uint4*)hh;
#pragma unroll
            for (int j = 0; j < 8; j++) { s[br] += a[br][j]; q[br] = fmaf(a[br][j], a[br][j], q[br]); }
        }
    }

    int warp = tid / 32, lane = tid % 32;
#pragma unroll
    for (int br = 0; br < 4; br++) {
        float ss = s[br], qq = q[br];
        for (int o = 16; o > 0; o >>= 1) {
            ss += __shfl_down_sync(~0u, ss, o);
            qq += __shfl_down_sync(~0u, qq, o);
        }
        if (lane == 0) { rsum[br][warp] = ss; rsq[br][warp] = qq; }
    }
    __syncthreads();
    if (tid < 4) {
        float ts = 0.f, tq = 0.f;
        for (int i = 0; i < 8; i++) { ts += rsum[tid][i]; tq += rsq[tid][i]; }
        int g = c >> 6;
        atomicAdd(&g_ssum[(tid * BN + b) * GROUPS + g], ts);
        atomicAdd(&g_ssq [(tid * BN + b) * GROUPS + g], tq);
    }
}

// ---------------- K2: groupnorm + sigmoid + weighted fuse (fp16 in, fp32+fp16 out) ----------------
__global__ void k_fuse(const float* __restrict__ gn_w, const float* __restrict__ gn_b) {
    int idx8 = blockIdx.x * 256 + threadIdx.x;   // uint4-of-halfs index (8 elems)
    int base = idx8 * 8;
    int b = base / (CN * NN);
    int c = (base / NN) % CN;
    int g = c >> 6;
    const float cnt = 64.f * 4096.f;
    float res[8];
#pragma unroll
    for (int t = 0; t < 8; t++) res[t] = 0.f;
#pragma unroll
    for (int br = 0; br < 4; br++) {
        float sS  = g_ssum[(br * BN + b) * GROUPS + g];
        float sq = g_ssq [(br * BN + b) * GROUPS + g];
        float mean = sS / cnt;
        float var = sq / cnt - mean * mean;
        float rstd = rsqrtf(var + 1e-5f);
        float gamma = gn_w[br * CN + c] * rstd;
        float beta = gn_b[br * CN + c] - mean * gamma;
        float wt = g_fw[br];
        uint4 raw = *(const uint4*)(&g_convh[br][base]);
        const __half2* h2 = (const __half2*)&raw;
#pragma unroll
        for (int t = 0; t < 4; t++) {
            float2 f = __half22float2(h2[t]);
            res[2 * t]     += wt / (1.f + __expf(-(f.x * gamma + beta)));
            res[2 * t + 1] += wt / (1.f + __expf(-(f.y * gamma + beta)));
        }
    }
    *(float4*)(g_fused + base)     = make_float4(res[0], res[1], res[2], res[3]);
    *(float4*)(g_fused + base + 4) = make_float4(res[4], res[5], res[6], res[7]);
    __half2 hh[4];
#pragma unroll
    for (int t = 0; t < 4; t++) hh[t] = __floats2half2_rn(res[2 * t], res[2 * t + 1]);
    *(uint4*)(&g_fa[base]) = *(uint4*)hh;
}

// ---------------- tensor-core helpers ----------------
__device__ __forceinline__ unsigned s2u(const void* p) {
    return (unsigned)__cvta_generic_to_shared(p);
}
__device__ __forceinline__ void cpa16(unsigned dst, const void* src) {
    asm volatile("cp.async.cg.shared.global [%0], [%1], 16;" :: "r"(dst), "l"(src));
}
__device__ __forceinline__ void cpcommit() {
    asm volatile("cp.async.commit_group;");
}
template <int N>
__device__ __forceinline__ void cpwait() {
    asm volatile("cp.async.wait_group %0;" :: "n"(N));
}
__device__ __forceinline__ void ldsm4t(unsigned* r, unsigned addr) {
    asm volatile("ldmatrix.sync.aligned.m8n8.x4.trans.shared.b16 {%0,%1,%2,%3}, [%4];"
        : "=r"(r[0]), "=r"(r[1]), "=r"(r[2]), "=r"(r[3]) : "r"(addr));
}
__device__ __forceinline__ void mma16816(float* c, const unsigned* a, const unsigned* b) {
    asm volatile(
        "mma.sync.aligned.m16n8k16.row.col.f32.f16.f16.f32 "
        "{%0,%1,%2,%3}, {%4,%5,%6,%7}, {%8,%9}, {%0,%1,%2,%3};"
        : "+f"(c[0]), "+f"(c[1]), "+f"(c[2]), "+f"(c[3])
        : "r"(a[0]), "r"(a[1]), "r"(a[2]), "r"(a[3]), "r"(b[0]), "r"(b[1]));
}

// ---------------- K3: QK GEMM fp16 mma + elu + RoPE epilogue ----------------
// block 128(m tokens) x 128(n chans), full K=256 resident in smem, cp.async staged.
#define GPITCH 136   // halfs per smem row (128 + 8 pad)
__global__ __launch_bounds__(256) void k_gemm_tc(void) {
    extern __shared__ __align__(16) __half sm[];
    __half* As = sm;                 // [256 k][GPITCH m]
    __half* Bs = sm + 256 * GPITCH;  // [256 k][GPITCH j]

    const int tid = threadIdx.x;
    const int warp = tid >> 5;
    const int lane = tid & 31;
    const int gid = lane >> 2, tig = lane & 3;
    const int wm = warp & 3;     // 4 m-tiles of 32
    const int wn = warp >> 2;    // 2 n-tiles of 64

    const int m0 = blockIdx.x * 128;
    const int j0 = blockIdx.y * 128;
    const int bidx = m0 / NN;
    const int ntok = m0 % NN;

    // ---- issue all loads: 8 groups of K=32 rows each (A + B) ----
    const unsigned sA = s2u(As), sB = s2u(Bs);
    const __half* srcA = g_fa + (size_t)bidx * CN * NN + ntok;
#pragma unroll
    for (int g = 0; g < 8; g++) {
#pragma unroll
        for (int rep = 0; rep < 2; rep++) {
            int cidx = tid + rep * 256;          // 0..511
            int kl = g * 32 + (cidx >> 4);
            int off = (cidx & 15) * 8;
            cpa16(sA + (kl * GPITCH + off) * 2, srcA + (size_t)kl * NN + off);
            cpa16(sB + (kl * GPITCH + off) * 2, g_wth + kl * 512 + j0 + off);
        }
        cpcommit();
    }

    // ---- ldmatrix address precompute ----
    const int l8 = lane >> 3, r8 = lane & 7;
    const int a_kr = r8 + ((l8 >> 1) << 3);
    const int a_mc = (l8 & 1) << 3;
    const int b_kr = r8 + ((l8 & 1) << 3);
    const int b_nc = (l8 >> 1) << 3;
    unsigned aaddr[2], baddr[4];
#pragma unroll
    for (int fm = 0; fm < 2; fm++)
        aaddr[fm] = sA + (a_kr * GPITCH + wm * 32 + fm * 16 + a_mc) * 2;
#pragma unroll
    for (int p = 0; p < 4; p++)
        baddr[p] = sB + (b_kr * GPITCH + wn * 64 + p * 16 + b_nc) * 2;

    float acc[2][8][4];
#pragma unroll
    for (int fm = 0; fm < 2; fm++)
#pragma unroll
        for (int fn = 0; fn < 8; fn++)
#pragma unroll
            for (int t = 0; t < 4; t++) acc[fm][fn][t] = 0.f;

    // ---- staged compute: wait group kt, compute its two k16 slices ----
#pragma unroll
    for (int kt = 0; kt < 8; kt++) {
        switch (kt) {
            case 0: cpwait<7>(); break; case 1: cpwait<6>(); break;
            case 2: cpwait<5>(); break; case 3: cpwait<4>(); break;
            case 4: cpwait<3>(); break; case 5: cpwait<2>(); break;
            case 6: cpwait<1>(); break; default: cpwait<0>(); break;
        }
        __syncthreads();
#pragma unroll
        for (int h16 = 0; h16 < 2; h16++) {
            const unsigned koff = (unsigned)(kt * 32 + h16 * 16) * (GPITCH * 2);
            unsigned a[2][4], b[8][2];
            ldsm4t(a[0], aaddr[0] + koff);
            ldsm4t(a[1], aaddr[1] + koff);
#pragma unroll
            for (int p = 0; p < 4; p++) {
                unsigned t[4];
                ldsm4t(t, baddr[p] + koff);
                b[2 * p][0] = t[0]; b[2 * p][1] = t[1];
                b[2 * p + 1][0] = t[2]; b[2 * p + 1][1] = t[3];
            }
#pragma unroll
            for (int fm = 0; fm < 2; fm++)
#pragma unroll
                for (int fn = 0; fn < 8; fn++)
                    mma16816(acc[fm][fn], a[fm], b[fn]);
        }
    }

    // ---- epilogue: elu+1, RoPE, planar scatter ----
    float* plain = (j0 < 256) ? g_qp : g_kp;
    float* roped = (j0 < 256) ? g_qr : g_kr;
    const int cb_base = (j0 & 255) + wn * 64;

#pragma unroll
    for (int fm = 0; fm < 2; fm++) {
        int t0 = wm * 32 + fm * 16 + gid;
        int wi0 = t0 & 63, wi1 = (t0 + 8) & 63;
#pragma unroll
        for (int fn = 0; fn < 8; fn++) {
            int cb = cb_base + fn * 8 + 2 * tig;
            int kidx = cb >> 1;
            float v0 = acc[fm][fn][0], v1 = acc[fm][fn][1];
            float v2 = acc[fm][fn][2], v3 = acc[fm][fn][3];
            float e0 = v0 > 0.f ? v0 + 1.f : __expf(v0);
            float e1 = v1 > 0.f ? v1 + 1.f : __expf(v1);
            float e2 = v2 > 0.f ? v2 + 1.f : __expf(v2);
            float e3 = v3 > 0.f ? v3 + 1.f : __expf(v3);
            float cs0 = g_cos[wi0 * 128 + kidx], sn0 = g_sin[wi0 * 128 + kidx];
            float cs1 = g_cos[wi1 * 128 + kidx], sn1 = g_sin[wi1 * 128 + kidx];
            size_t base = ((size_t)(bidx * CN + cb)) * NN + ntok + t0;
            plain[base]          = e0;
            plain[base + NN]     = e1;
            plain[base + 8]      = e2;
            plain[base + NN + 8] = e3;
            roped[base]          = cs0 * e0 - sn0 * e1;
            roped[base + NN]     = sn0 * e0 + cs0 * e1;
            roped[base + 8]      = cs1 * e2 - sn1 * e3;
            roped[base + NN + 8] = sn1 * e2 + cs1 * e3;
        }
    }
}

// ---------------- K4: k_mean over n ----------------
__global__ void k_kmean() {
    int warp = threadIdx.x / 32, lane = threadIdx.x % 32;
    int row = blockIdx.x * 8 + warp;
    const float* p = g_kp + (size_t)row * NN;
    float s = 0.f;
    for (int i = lane; i < NN / 4; i += 32) {
        float4 v = ((const float4*)p)[i];
        s += v.x + v.y + v.z + v.w;
    }
    for (int o = 16; o > 0; o >>= 1) s += __shfl_down_sync(~0u, s, o);
    if (lane == 0) g_kmean[row] = s * (1.f / 4096.f);
}

// ---------------- K5: z = 1 / (q . k_mean + 1e-6) ----------------
__global__ void k_z() {
    int bh = blockIdx.x;
    int b = bh / HEADS, h = bh % HEADS;
    __shared__ float km[64];
    int tid = threadIdx.x;
    if (tid < 64) km[tid] = g_kmean[b * CN + h * 64 + tid];
    __syncthreads();
    float acc[16];
#pragma unroll
    for (int i = 0; i < 16; i++) acc[i] = 0.f;
    for (int c = 0; c < 64; c++) {
        const float* row = g_qp + ((size_t)(b * CN + h * 64 + c)) * NN;
        float kmv = km[c];
#pragma unroll
        for (int i = 0; i < 16; i++) acc[i] = fmaf(row[tid + i * 256], kmv, acc[i]);
    }
    float* zp = g_z + (size_t)bh * NN;
#pragma unroll
    for (int i = 0; i < 16; i++) zp[tid + i * 256] = 1.f / (acc[i] + 1e-6f);
}

// ---------------- K6: kv = k_rope^T @ v / n ----------------
__global__ __launch_bounds__(256) void k_kv() {
    int bh = blockIdx.x;
    int chunk = blockIdx.y;
    int b = bh / HEADS, h = bh % HEADS;
    __shared__ float Ks[32][68];
    __shared__ float Vs[32][68];
    int tid = threadIdx.x;
    int ld_d = tid / 4;
    int ld_n8 = (tid % 4) * 8;
    int d0 = (tid / 16) * 4, e0 = (tid % 16) * 4;
    float kvacc[4][4];
#pragma unroll
    for (int i = 0; i < 4; i++)
#pragma unroll
        for (int j = 0; j < 4; j++) kvacc[i][j] = 0.f;

    int nstart = chunk * 1024;
    for (int it = 0; it < 32; it++) {
        int n0 = nstart + it * 32;
        const float* kp = g_kr + ((size_t)(b * CN + h * 64 + ld_d)) * NN + n0 + ld_n8;
        const float* vp = g_fused + ((size_t)(b * CN + h * 64 + ld_d)) * NN + n0 + ld_n8;
        float kvl[8], vvl[8];
        *(float4*)&kvl[0] = ((const float4*)kp)[0];
        *(float4*)&kvl[4] = ((const float4*)kp)[1];
        *(float4*)&vvl[0] = ((const float4*)vp)[0];
        *(float4*)&vvl[4] = ((const float4*)vp)[1];
        __syncthreads();
#pragma unroll
        for (int t = 0; t < 8; t++) {
            Ks[ld_n8 + t][ld_d] = kvl[t];
            Vs[ld_n8 + t][ld_d] = vvl[t];
        }
        __syncthreads();
#pragma unroll
        for (int nn = 0; nn < 32; nn++) {
            float kd[4], ve[4];
            *(float4*)kd = *(float4*)&Ks[nn][d0];
            *(float4*)ve = *(float4*)&Vs[nn][e0];
#pragma unroll
            for (int di = 0; di < 4; di++)
#pragma unroll
                for (int ei = 0; ei < 4; ei++)
                    kvacc[di][ei] = fmaf(kd[di], ve[ei], kvacc[di][ei]);
        }
    }
    const float scale = 1.f / 4096.f;
#pragma unroll
    for (int di = 0; di < 4; di++)
#pragma unroll
        for (int ei = 0; ei < 4; ei++)
            atomicAdd(&g_kv[((size_t)bh * 64 + d0 + di) * 64 + e0 + ei], kvacc[di][ei] * scale);
}

// ---------------- K7: lepe 3x3 dwconv on fused -> out ----------------
__global__ __launch_bounds__(256) void k_lepe(const float* __restrict__ w,
                                              const float* __restrict__ bias,
                                              float* __restrict__ out) {
    __shared__ float tile[72 * 72];
    __shared__ float wsm[9];
    const int c = blockIdx.x, b = blockIdx.y;
    const int tid = threadIdx.x;
    const size_t plane = ((size_t)(b * CN + c)) * NN;
    const float* xp = g_fused + plane;
    for (int i = tid; i < 72 * 72; i += 256) {
        int ty = i / 72, tx = i % 72;
        int gy = ty - 4, gx = tx - 4;
        float v = 0.f;
        if (gy >= 0 && gy < 64 && gx >= 0 && gx < 64) v = xp[gy * 64 + gx];
        tile[i] = v;
    }
    if (tid < 9) wsm[tid] = w[c * 9 + tid];
    __syncthreads();

    const float bv = bias[c];
    float* op = out + plane;
#pragma unroll
    for (int seg = 0; seg < 2; seg++) {
        int sidx = tid + seg * 256;
        int h = sidx / 8;
        int w0 = (sidx % 8) * 8;
        float acc[8];
#pragma unroll
        for (int j = 0; j < 8; j++) acc[j] = bv;
#pragma unroll
        for (int dy = 0; dy < 3; dy++) {
            const float* trow = &tile[(h + dy + 3) * 72 + (w0 + 3)];
            float rv[10];
#pragma unroll
            for (int xi = 0; xi < 10; xi++) rv[xi] = trow[xi];
#pragma unroll
            for (int dx = 0; dx < 3; dx++) {
                float wv = wsm[dy * 3 + dx];
#pragma unroll
                for (int j = 0; j < 8; j++) acc[j] = fmaf(rv[dx + j], wv, acc[j]);
            }
        }
        float4* o4 = (float4*)(op + h * 64 + w0);
        o4[0] = make_float4(acc[0], acc[1], acc[2], acc[3]);
        o4[1] = make_float4(acc[4], acc[5], acc[6], acc[7]);
    }
}

// ---------------- K8: out += z * (q_rope @ kv) ----------------
__global__ __launch_bounds__(256) void k_attn(float* __restrict__ out) {
    int bh = blockIdx.x;
    int nc = blockIdx.y;
    int b = bh / HEADS, h = bh % HEADS;
    __shared__ float KVs[64][64];
    __shared__ float Qs[64][64];
    __shared__ float zs[64];
    int tid = threadIdx.x;
    int n0 = nc * 64;
    {
        const float* kvp = g_kv + (size_t)bh * 4096;
#pragma unroll
        for (int i = 0; i < 4; i++) {
            int idx = tid * 16 + i * 4;
            *(float4*)&((float*)KVs)[idx] = *(const float4*)&kvp[idx];
        }
        int d = tid / 4, ns = (tid % 4) * 16;
        const float* qp = g_qr + ((size_t)(b * CN + h * 64 + d)) * NN + n0 + ns;
#pragma unroll
        for (int i = 0; i < 4; i++) *(float4*)&Qs[d][ns + i * 4] = ((const float4*)qp)[i];
        if (tid < 64) zs[tid] = g_z[(size_t)bh * NN + n0 + tid];
    }
    __syncthreads();

    int nl = tid / 4, e0 = (tid % 4) * 16;
    float acc[16];
#pragma unroll
    for (int i = 0; i < 16; i++) acc[i] = 0.f;
#pragma unroll
    for (int d = 0; d < 64; d++) {
        float qv = Qs[d][nl];
#pragma unroll
        for (int i = 0; i < 4; i++) {
            float4 kvv = *(float4*)&KVs[d][e0 + i * 4];
            acc[i * 4 + 0] = fmaf(qv, kvv.x, acc[i * 4 + 0]);
            acc[i * 4 + 1] = fmaf(qv, kvv.y, acc[i * 4 + 1]);
            acc[i * 4 + 2] = fmaf(qv, kvv.z, acc[i * 4 + 2]);
            acc[i * 4 + 3] = fmaf(qv, kvv.w, acc[i * 4 + 3]);
        }
    }
    float zv = zs[nl];
    int n = n0 + nl;
#pragma unroll
    for (int ei = 0; ei < 16; ei++) {
        size_t off = ((size_t)(b * CN + h * 64 + e0 + ei)) * NN + n;
        out[off] += acc[ei] * zv;
    }
}

// ---------------- launch ----------------
extern "C" void kernel_launch(void* const* d_in, const int* in_sizes, int n_in,
                              void* d_out, int out_size) {
    const float* x   = (const float*)d_in[0];
    const float* cw0 = (const float*)d_in[1];
    const float* cb0 = (const float*)d_in[2];
    const float* cw1 = (const float*)d_in[3];
    const float* cb1 = (const float*)d_in[4];
    const float* cw2 = (const float*)d_in[5];
    const float* cb2 = (const float*)d_in[6];
    const float* cw3 = (const float*)d_in[7];
    const float* cb3 = (const float*)d_in[8];
    const float* gn_w = (const float*)d_in[9];
    const float* gn_b = (const float*)d_in[10];
    const float* fw   = (const float*)d_in[11];
    const float* qkw  = (const float*)d_in[12];
    const float* lepe_w = (const float*)d_in[13];
    const float* lepe_b = (const float*)d_in[14];
    float* out = (float*)d_out;

    static bool attr_set = false;
    const int GEMM_SMEM = 2 * 256 * GPITCH * 2;   // 139264 bytes
    if (!attr_set) {
        cudaFuncSetAttribute(k_gemm_tc, cudaFuncAttributeMaxDynamicSharedMemorySize, GEMM_SMEM);
        attr_set = true;
    }

    k_init<<<1024, 256>>>(fw);
    k_wtrans<<<512, 256>>>(qkw);

    dim3 gconv(CN, BN);
    k_conv4<<<gconv, 256>>>(x, cw0, cb0, cw1, cb1, cw2, cb2, cw3, cb3);

    k_fuse<<<BN * CN * NN / 8 / 256, 256>>>(gn_w, gn_b);

    dim3 ggemm(512, 4);
    k_gemm_tc<<<ggemm, 256, GEMM_SMEM>>>();

    k_kmean<<<BN * CN / 8, 256>>>();
    k_z<<<BN * HEADS, 256>>>();

    dim3 gkv(BN * HEADS, 4);
    k_kv<<<gkv, 256>>>();

    k_lepe<<<gconv, 256>>>(lepe_w, lepe_b, out);

    dim3 gattn(BN * HEADS, NN / 64);
    k_attn<<<gattn, 256>>>(out);
}

// round 15
// speedup vs baseline: 1.0027x; 1.0017x over previous
#include <cuda_runtime.h>
#include <cuda_fp16.h>
#include <math.h>

#define BN 16
#define CN 256
#define NN 4096          // H*W
#define HEADS 4
#define HD 64
#define GROUPS 4

// ---------------- scratch (__device__ globals: allocation-free) ----------------
__device__ __align__(128) __half g_convh[4][BN * CN * NN]; // conv outputs fp16
__device__ float g_fused[BN * CN * NN];     // fused (fp32, v path)
__device__ __align__(128) __half g_fa[BN * CN * NN];       // fused fp16 (GEMM A)
__device__ __align__(128) __half g_wth[256 * 512];         // qk_w^T fp16: [k][j]
__device__ float g_qp[BN * CN * NN];
__device__ float g_kp[BN * CN * NN];
__device__ float g_qr[BN * CN * NN];
__device__ float g_kr[BN * CN * NN];
__device__ float g_kmean[BN * CN];
__device__ float g_z[BN * HEADS * NN];
__device__ float g_kv[BN * HEADS * HD * HD];
__device__ float g_cos[64 * 128];
__device__ float g_sin[64 * 128];
__device__ float g_fw[4];
__device__ float g_ssum[4 * BN * GROUPS];
__device__ float g_ssq[4 * BN * GROUPS];

// ---------------- K0: init ----------------
__global__ void k_init(const float* __restrict__ fusion_w) {
    int idx = blockIdx.x * 256 + threadIdx.x;
    if (idx < BN * HEADS * HD * HD) g_kv[idx] = 0.f;
    if (idx < 4 * BN * GROUPS) { g_ssum[idx] = 0.f; g_ssq[idx] = 0.f; }
    if (idx < 64 * 128) {
        int w = idx / 128, k = idx % 128;
        float theta = powf(10000.f, -(float)k / 128.f);
        float ang = (float)w * theta;
        g_cos[idx] = cosf(ang);
        g_sin[idx] = sinf(ang);
    }
    if (idx == 0) {
        float m = fusion_w[0];
        for (int i = 1; i < 4; i++) m = fmaxf(m, fusion_w[i]);
        float e[4], s = 0.f;
        for (int i = 0; i < 4; i++) { e[i] = expf(fusion_w[i] - m); s += e[i]; }
        for (int i = 0; i < 4; i++) g_fw[i] = e[i] / s;
    }
}

// ---------------- transpose qk_w [512,256] -> g_wth [256][512] fp16 ----------------
__global__ void k_wtrans(const float* __restrict__ qkw) {
    int id = blockIdx.x * 256 + threadIdx.x;   // 512*256 total
    int k = id / 512, j = id % 512;
    g_wth[id] = __float2half(qkw[j * 256 + k]);
}

// ---------------- K1: all 4 depthwise convs fused, one tile load ----------------
__global__ __launch_bounds__(256) void k_conv4(
    const float* __restrict__ x,
    const float* __restrict__ w3, const float* __restrict__ b3,
    const float* __restrict__ w5, const float* __restrict__ b5,
    const float* __restrict__ w7, const float* __restrict__ b7,
    const float* __restrict__ w9, const float* __restrict__ b9) {
    __shared__ float tile[72 * 72];
    __shared__ float ws3[9], ws5[25], ws7[49], ws9[81];
    __shared__ float rsum[4][8], rsq[4][8];
    const int c = blockIdx.x, b = blockIdx.y;
    const int tid = threadIdx.x;
    const size_t plane = ((size_t)(b * CN + c)) * NN;
    const float* xp = x + plane;
    for (int i = tid; i < 72 * 72; i += 256) {
        int ty = i / 72, tx = i % 72;
        int gy = ty - 4, gx = tx - 4;
        float v = 0.f;
        if (gy >= 0 && gy < 64 && gx >= 0 && gx < 64) v = xp[gy * 64 + gx];
        tile[i] = v;
    }
    if (tid < 9)  ws3[tid] = w3[c * 9 + tid];
    if (tid < 25) ws5[tid] = w5[c * 25 + tid];
    if (tid < 49) ws7[tid] = w7[c * 49 + tid];
    if (tid < 81) ws9[tid] = w9[c * 81 + tid];
    __syncthreads();

    const float bv[4] = {b3[c], b5[c], b7[c], b9[c]};
    float s[4] = {0.f, 0.f, 0.f, 0.f}, q[4] = {0.f, 0.f, 0.f, 0.f};

#pragma unroll
    for (int seg = 0; seg < 2; seg++) {
        int sidx = tid + seg * 256;
        int h = sidx / 8;
        int w0 = (sidx % 8) * 8;
        float a[4][8];
#pragma unroll
        for (int br = 0; br < 4; br++)
#pragma unroll
            for (int j = 0; j < 8; j++) a[br][j] = bv[br];

#pragma unroll
        for (int dy = 0; dy < 9; dy++) {
            const float* trow = &tile[(h + dy) * 72 + w0];
            float rv[16];
#pragma unroll
            for (int xi = 0; xi < 16; xi++) rv[xi] = trow[xi];
            // k9 (pad 4): rows 0..8, cols rv[dx + j]
#pragma unroll
            for (int dx = 0; dx < 9; dx++) {
                float wv = ws9[dy * 9 + dx];
#pragma unroll
                for (int j = 0; j < 8; j++) a[3][j] = fmaf(rv[dx + j], wv, a[3][j]);
            }
            if (dy >= 1 && dy <= 7) {   // k7
                int d7 = dy - 1;
#pragma unroll
                for (int dx = 0; dx < 7; dx++) {
                    float wv = ws7[d7 * 7 + dx];
#pragma unroll
                    for (int j = 0; j < 8; j++) a[2][j] = fmaf(rv[dx + 1 + j], wv, a[2][j]);
                }
            }
            if (dy >= 2 && dy <= 6) {   // k5
                int d5 = dy - 2;
#pragma unroll
                for (int dx = 0; dx < 5; dx++) {
                    float wv = ws5[d5 * 5 + dx];
#pragma unroll
                    for (int j = 0; j < 8; j++) a[1][j] = fmaf(rv[dx + 2 + j], wv, a[1][j]);
                }
            }
            if (dy >= 3 && dy <= 5) {   // k3
                int d3 = dy - 3;
#pragma unroll
                for (int dx = 0; dx < 3; dx++) {
                    float wv = ws3[d3 * 3 + dx];
#pragma unroll
                    for (int j = 0; j < 8; j++) a[0][j] = fmaf(rv[dx + 3 + j], wv, a[0][j]);
                }
            }
        }

#pragma unroll
        for (int br = 0; br < 4; br++) {
            __half2 hh[4];
#pragma unroll
            for (int t = 0; t < 4; t++) hh[t] = __floats2half2_rn(a[br][2 * t], a[br][2 * t + 1]);
            *(uint4*)(&g_convh[br][plane + h * 64 + w0]) = *(uint4*)hh;
#pragma unroll
            for (int j = 0; j < 8; j++) { s[br] += a[br][j]; q[br] = fmaf(a[br][j], a[br][j], q[br]); }
        }
    }

    int warp = tid / 32, lane = tid % 32;
#pragma unroll
    for (int br = 0; br < 4; br++) {
        float ss = s[br], qq = q[br];
        for (int o = 16; o > 0; o >>= 1) {
            ss += __shfl_down_sync(~0u, ss, o);
            qq += __shfl_down_sync(~0u, qq, o);
        }
        if (lane == 0) { rsum[br][warp] = ss; rsq[br][warp] = qq; }
    }
    __syncthreads();
    if (tid < 4) {
        float ts = 0.f, tq = 0.f;
        for (int i = 0; i < 8; i++) { ts += rsum[tid][i]; tq += rsq[tid][i]; }
        int g = c >> 6;
        atomicAdd(&g_ssum[(tid * BN + b) * GROUPS + g], ts);
        atomicAdd(&g_ssq [(tid * BN + b) * GROUPS + g], tq);
    }
}

// ---------------- K2: groupnorm + sigmoid + weighted fuse (fp16 in, fp32+fp16 out) ----------------
__global__ void k_fuse(const float* __restrict__ gn_w, const float* __restrict__ gn_b) {
    int idx8 = blockIdx.x * 256 + threadIdx.x;   // uint4-of-halfs index (8 elems)
    int base = idx8 * 8;
    int b = base / (CN * NN);
    int c = (base / NN) % CN;
    int g = c >> 6;
    const float cnt = 64.f * 4096.f;
    float res[8];
#pragma unroll
    for (int t = 0; t < 8; t++) res[t] = 0.f;
#pragma unroll
    for (int br = 0; br < 4; br++) {
        float sS  = g_ssum[(br * BN + b) * GROUPS + g];
        float sq = g_ssq [(br * BN + b) * GROUPS + g];
        float mean = sS / cnt;
        float var = sq / cnt - mean * mean;
        float rstd = rsqrtf(var + 1e-5f);
        float gamma = gn_w[br * CN + c] * rstd;
        float beta = gn_b[br * CN + c] - mean * gamma;
        float wt = g_fw[br];
        uint4 raw = *(const uint4*)(&g_convh[br][base]);
        const __half2* h2 = (const __half2*)&raw;
#pragma unroll
        for (int t = 0; t < 4; t++) {
            float2 f = __half22float2(h2[t]);
            res[2 * t]     += wt / (1.f + __expf(-(f.x * gamma + beta)));
            res[2 * t + 1] += wt / (1.f + __expf(-(f.y * gamma + beta)));
        }
    }
    *(float4*)(g_fused + base)     = make_float4(res[0], res[1], res[2], res[3]);
    *(float4*)(g_fused + base + 4) = make_float4(res[4], res[5], res[6], res[7]);
    __half2 hh[4];
#pragma unroll
    for (int t = 0; t < 4; t++) hh[t] = __floats2half2_rn(res[2 * t], res[2 * t + 1]);
    *(uint4*)(&g_fa[base]) = *(uint4*)hh;
}

// ---------------- tensor-core helpers ----------------
__device__ __forceinline__ unsigned s2u(const void* p) {
    return (unsigned)__cvta_generic_to_shared(p);
}
__device__ __forceinline__ void cpa16(unsigned dst, const void* src) {
    asm volatile("cp.async.cg.shared.global [%0], [%1], 16;" :: "r"(dst), "l"(src));
}
__device__ __forceinline__ void cpcommit() {
    asm volatile("cp.async.commit_group;");
}
template <int N>
__device__ __forceinline__ void cpwait() {
    asm volatile("cp.async.wait_group %0;" :: "n"(N));
}
__device__ __forceinline__ void ldsm4t(unsigned* r, unsigned addr) {
    asm volatile("ldmatrix.sync.aligned.m8n8.x4.trans.shared.b16 {%0,%1,%2,%3}, [%4];"
        : "=r"(r[0]), "=r"(r[1]), "=r"(r[2]), "=r"(r[3]) : "r"(addr));
}
__device__ __forceinline__ void mma16816(float* c, const unsigned* a, const unsigned* b) {
    asm volatile(
        "mma.sync.aligned.m16n8k16.row.col.f32.f16.f16.f32 "
        "{%0,%1,%2,%3}, {%4,%5,%6,%7}, {%8,%9}, {%0,%1,%2,%3};"
        : "+f"(c[0]), "+f"(c[1]), "+f"(c[2]), "+f"(c[3])
        : "r"(a[0]), "r"(a[1]), "r"(a[2]), "r"(a[3]), "r"(b[0]), "r"(b[1]));
}

// ---------------- K3: QK GEMM fp16 mma + elu + RoPE epilogue ----------------
// block 128(m tokens) x 128(n chans), full K=256 resident in smem, cp.async staged.
#define GPITCH 136   // halfs per smem row (128 + 8 pad)
__global__ __launch_bounds__(256) void k_gemm_tc(void) {
    extern __shared__ __align__(16) __half sm[];
    __half* As = sm;                 // [256 k][GPITCH m]
    __half* Bs = sm + 256 * GPITCH;  // [256 k][GPITCH j]

    const int tid = threadIdx.x;
    const int warp = tid >> 5;
    const int lane = tid & 31;
    const int gid = lane >> 2, tig = lane & 3;
    const int wm = warp & 3;     // 4 m-tiles of 32
    const int wn = warp >> 2;    // 2 n-tiles of 64

    const int m0 = blockIdx.x * 128;
    const int j0 = blockIdx.y * 128;
    const int bidx = m0 / NN;
    const int ntok = m0 % NN;

    // ---- issue all loads: 8 groups of K=32 rows each (A + B) ----
    const unsigned sA = s2u(As), sB = s2u(Bs);
    const __half* srcA = g_fa + (size_t)bidx * CN * NN + ntok;
#pragma unroll
    for (int g = 0; g < 8; g++) {
#pragma unroll
        for (int rep = 0; rep < 2; rep++) {
            int cidx = tid + rep * 256;          // 0..511
            int kl = g * 32 + (cidx >> 4);
            int off = (cidx & 15) * 8;
            cpa16(sA + (kl * GPITCH + off) * 2, srcA + (size_t)kl * NN + off);
            cpa16(sB + (kl * GPITCH + off) * 2, g_wth + kl * 512 + j0 + off);
        }
        cpcommit();
    }

    // ---- ldmatrix address precompute ----
    const int l8 = lane >> 3, r8 = lane & 7;
    const int a_kr = r8 + ((l8 >> 1) << 3);
    const int a_mc = (l8 & 1) << 3;
    const int b_kr = r8 + ((l8 & 1) << 3);
    const int b_nc = (l8 >> 1) << 3;
    unsigned aaddr[2], baddr[4];
#pragma unroll
    for (int fm = 0; fm < 2; fm++)
        aaddr[fm] = sA + (a_kr * GPITCH + wm * 32 + fm * 16 + a_mc) * 2;
#pragma unroll
    for (int p = 0; p < 4; p++)
        baddr[p] = sB + (b_kr * GPITCH + wn * 64 + p * 16 + b_nc) * 2;

    float acc[2][8][4];
#pragma unroll
    for (int fm = 0; fm < 2; fm++)
#pragma unroll
        for (int fn = 0; fn < 8; fn++)
#pragma unroll
            for (int t = 0; t < 4; t++) acc[fm][fn][t] = 0.f;

    // ---- staged compute: wait group kt, compute its two k16 slices ----
#pragma unroll
    for (int kt = 0; kt < 8; kt++) {
        switch (kt) {
            case 0: cpwait<7>(); break; case 1: cpwait<6>(); break;
            case 2: cpwait<5>(); break; case 3: cpwait<4>(); break;
            case 4: cpwait<3>(); break; case 5: cpwait<2>(); break;
            case 6: cpwait<1>(); break; default: cpwait<0>(); break;
        }
        __syncthreads();
#pragma unroll
        for (int h16 = 0; h16 < 2; h16++) {
            const unsigned koff = (unsigned)(kt * 32 + h16 * 16) * (GPITCH * 2);
            unsigned a[2][4], b[8][2];
            ldsm4t(a[0], aaddr[0] + koff);
            ldsm4t(a[1], aaddr[1] + koff);
#pragma unroll
            for (int p = 0; p < 4; p++) {
                unsigned t[4];
                ldsm4t(t, baddr[p] + koff);
                b[2 * p][0] = t[0]; b[2 * p][1] = t[1];
                b[2 * p + 1][0] = t[2]; b[2 * p + 1][1] = t[3];
            }
#pragma unroll
            for (int fm = 0; fm < 2; fm++)
#pragma unroll
                for (int fn = 0; fn < 8; fn++)
                    mma16816(acc[fm][fn], a[fm], b[fn]);
        }
    }

    // ---- epilogue: elu+1, RoPE, planar scatter ----
    float* plain = (j0 < 256) ? g_qp : g_kp;
    float* roped = (j0 < 256) ? g_qr : g_kr;
    const int cb_base = (j0 & 255) + wn * 64;

#pragma unroll
    for (int fm = 0; fm < 2; fm++) {
        int t0 = wm * 32 + fm * 16 + gid;
        int wi0 = t0 & 63, wi1 = (t0 + 8) & 63;
#pragma unroll
        for (int fn = 0; fn < 8; fn++) {
            int cb = cb_base + fn * 8 + 2 * tig;
            int kidx = cb >> 1;
            float v0 = acc[fm][fn][0], v1 = acc[fm][fn][1];
            float v2 = acc[fm][fn][2], v3 = acc[fm][fn][3];
            float e0 = v0 > 0.f ? v0 + 1.f : __expf(v0);
            float e1 = v1 > 0.f ? v1 + 1.f : __expf(v1);
            float e2 = v2 > 0.f ? v2 + 1.f : __expf(v2);
            float e3 = v3 > 0.f ? v3 + 1.f : __expf(v3);
            float cs0 = g_cos[wi0 * 128 + kidx], sn0 = g_sin[wi0 * 128 + kidx];
            float cs1 = g_cos[wi1 * 128 + kidx], sn1 = g_sin[wi1 * 128 + kidx];
            size_t base = ((size_t)(bidx * CN + cb)) * NN + ntok + t0;
            plain[base]          = e0;
            plain[base + NN]     = e1;
            plain[base + 8]      = e2;
            plain[base + NN + 8] = e3;
            roped[base]          = cs0 * e0 - sn0 * e1;
            roped[base + NN]     = sn0 * e0 + cs0 * e1;
            roped[base + 8]      = cs1 * e2 - sn1 * e3;
            roped[base + NN + 8] = sn1 * e2 + cs1 * e3;
        }
    }
}

// ---------------- K4: k_mean over n ----------------
__global__ void k_kmean() {
    int warp = threadIdx.x / 32, lane = threadIdx.x % 32;
    int row = blockIdx.x * 8 + warp;
    const float* p = g_kp + (size_t)row * NN;
    float s = 0.f;
    for (int i = lane; i < NN / 4; i += 32) {
        float4 v = ((const float4*)p)[i];
        s += v.x + v.y + v.z + v.w;
    }
    for (int o = 16; o > 0; o >>= 1) s += __shfl_down_sync(~0u, s, o);
    if (lane == 0) g_kmean[row] = s * (1.f / 4096.f);
}

// ---------------- K5: z = 1 / (q . k_mean + 1e-6) ----------------
__global__ void k_z() {
    int bh = blockIdx.x;
    int b = bh / HEADS, h = bh % HEADS;
    __shared__ float km[64];
    int tid = threadIdx.x;
    if (tid < 64) km[tid] = g_kmean[b * CN + h * 64 + tid];
    __syncthreads();
    float acc[16];
#pragma unroll
    for (int i = 0; i < 16; i++) acc[i] = 0.f;
    for (int c = 0; c < 64; c++) {
        const float* row = g_qp + ((size_t)(b * CN + h * 64 + c)) * NN;
        float kmv = km[c];
#pragma unroll
        for (int i = 0; i < 16; i++) acc[i] = fmaf(row[tid + i * 256], kmv, acc[i]);
    }
    float* zp = g_z + (size_t)bh * NN;
#pragma unroll
    for (int i = 0; i < 16; i++) zp[tid + i * 256] = 1.f / (acc[i] + 1e-6f);
}

// ---------------- K6: kv = k_rope^T @ v / n ----------------
__global__ __launch_bounds__(256) void k_kv() {
    int bh = blockIdx.x;
    int chunk = blockIdx.y;
    int b = bh / HEADS, h = bh % HEADS;
    __shared__ float Ks[32][68];
    __shared__ float Vs[32][68];
    int tid = threadIdx.x;
    int ld_d = tid / 4;
    int ld_n8 = (tid % 4) * 8;
    int d0 = (tid / 16) * 4, e0 = (tid % 16) * 4;
    float kvacc[4][4];
#pragma unroll
    for (int i = 0; i < 4; i++)
#pragma unroll
        for (int j = 0; j < 4; j++) kvacc[i][j] = 0.f;

    int nstart = chunk * 1024;
    for (int it = 0; it < 32; it++) {
        int n0 = nstart + it * 32;
        const float* kp = g_kr + ((size_t)(b * CN + h * 64 + ld_d)) * NN + n0 + ld_n8;
        const float* vp = g_fused + ((size_t)(b * CN + h * 64 + ld_d)) * NN + n0 + ld_n8;
        float kvl[8], vvl[8];
        *(float4*)&kvl[0] = ((const float4*)kp)[0];
        *(float4*)&kvl[4] = ((const float4*)kp)[1];
        *(float4*)&vvl[0] = ((const float4*)vp)[0];
        *(float4*)&vvl[4] = ((const float4*)vp)[1];
        __syncthreads();
#pragma unroll
        for (int t = 0; t < 8; t++) {
            Ks[ld_n8 + t][ld_d] = kvl[t];
            Vs[ld_n8 + t][ld_d] = vvl[t];
        }
        __syncthreads();
#pragma unroll
        for (int nn = 0; nn < 32; nn++) {
            float kd[4], ve[4];
            *(float4*)kd = *(float4*)&Ks[nn][d0];
            *(float4*)ve = *(float4*)&Vs[nn][e0];
#pragma unroll
            for (int di = 0; di < 4; di++)
#pragma unroll
                for (int ei = 0; ei < 4; ei++)
                    kvacc[di][ei] = fmaf(kd[di], ve[ei], kvacc[di][ei]);
        }
    }
    const float scale = 1.f / 4096.f;
#pragma unroll
    for (int di = 0; di < 4; di++)
#pragma unroll
        for (int ei = 0; ei < 4; ei++)
            atomicAdd(&g_kv[((size_t)bh * 64 + d0 + di) * 64 + e0 + ei], kvacc[di][ei] * scale);
}

// ---------------- K7: lepe 3x3 dwconv on fused -> out ----------------
__global__ __launch_bounds__(256) void k_lepe(const float* __restrict__ w,
                                              const float* __restrict__ bias,
                                              float* __restrict__ out) {
    __shared__ float tile[72 * 72];
    __shared__ float wsm[9];
    const int c = blockIdx.x, b = blockIdx.y;
    const int tid = threadIdx.x;
    const size_t plane = ((size_t)(b * CN + c)) * NN;
    const float* xp = g_fused + plane;
    for (int i = tid; i < 72 * 72; i += 256) {
        int ty = i / 72, tx = i % 72;
        int gy = ty - 4, gx = tx - 4;
        float v = 0.f;
        if (gy >= 0 && gy < 64 && gx >= 0 && gx < 64) v = xp[gy * 64 + gx];
        tile[i] = v;
    }
    if (tid < 9) wsm[tid] = w[c * 9 + tid];
    __syncthreads();

    const float bv = bias[c];
    float* op = out + plane;
#pragma unroll
    for (int seg = 0; seg < 2; seg++) {
        int sidx = tid + seg * 256;
        int h = sidx / 8;
        int w0 = (sidx % 8) * 8;
        float acc[8];
#pragma unroll
        for (int j = 0; j < 8; j++) acc[j] = bv;
#pragma unroll
        for (int dy = 0; dy < 3; dy++) {
            const float* trow = &tile[(h + dy + 3) * 72 + (w0 + 3)];
            float rv[10];
#pragma unroll
            for (int xi = 0; xi < 10; xi++) rv[xi] = trow[xi];
#pragma unroll
            for (int dx = 0; dx < 3; dx++) {
                float wv = wsm[dy * 3 + dx];
#pragma unroll
                for (int j = 0; j < 8; j++) acc[j] = fmaf(rv[dx + j], wv, acc[j]);
            }
        }
        float4* o4 = (float4*)(op + h * 64 + w0);
        o4[0] = make_float4(acc[0], acc[1], acc[2], acc[3]);
        o4[1] = make_float4(acc[4], acc[5], acc[6], acc[7]);
    }
}

// ---------------- K8: out += z * (q_rope @ kv) ----------------
__global__ __launch_bounds__(256) void k_attn(float* __restrict__ out) {
    int bh = blockIdx.x;
    int nc = blockIdx.y;
    int b = bh / HEADS, h = bh % HEADS;
    __shared__ float KVs[64][64];
    __shared__ float Qs[64][64];
    __shared__ float zs[64];
    int tid = threadIdx.x;
    int n0 = nc * 64;
    {
        const float* kvp = g_kv + (size_t)bh * 4096;
#pragma unroll
        for (int i = 0; i < 4; i++) {
            int idx = tid * 16 + i * 4;
            *(float4*)&((float*)KVs)[idx] = *(const float4*)&kvp[idx];
        }
        int d = tid / 4, ns = (tid % 4) * 16;
        const float* qp = g_qr + ((size_t)(b * CN + h * 64 + d)) * NN + n0 + ns;
#pragma unroll
        for (int i = 0; i < 4; i++) *(float4*)&Qs[d][ns + i * 4] = ((const float4*)qp)[i];
        if (tid < 64) zs[tid] = g_z[(size_t)bh * NN + n0 + tid];
    }
    __syncthreads();

    int nl = tid / 4, e0 = (tid % 4) * 16;
    float acc[16];
#pragma unroll
    for (int i = 0; i < 16; i++) acc[i] = 0.f;
#pragma unroll
    for (int d = 0; d < 64; d++) {
        float qv = Qs[d][nl];
#pragma unroll
        for (int i = 0; i < 4; i++) {
            float4 kvv = *(float4*)&KVs[d][e0 + i * 4];
            acc[i * 4 + 0] = fmaf(qv, kvv.x, acc[i * 4 + 0]);
            acc[i * 4 + 1] = fmaf(qv, kvv.y, acc[i * 4 + 1]);
            acc[i * 4 + 2] = fmaf(qv, kvv.z, acc[i * 4 + 2]);
            acc[i * 4 + 3] = fmaf(qv, kvv.w, acc[i * 4 + 3]);
        }
    }
    float zv = zs[nl];
    int n = n0 + nl;
#pragma unroll
    for (int ei = 0; ei < 16; ei++) {
        size_t off = ((size_t)(b * CN + h * 64 + e0 + ei)) * NN + n;
        out[off] += acc[ei] * zv;
    }
}

// ---------------- launch ----------------
extern "C" void kernel_launch(void* const* d_in, const int* in_sizes, int n_in,
                              void* d_out, int out_size) {
    const float* x   = (const float*)d_in[0];
    const float* cw0 = (const float*)d_in[1];
    const float* cb0 = (const float*)d_in[2];
    const float* cw1 = (const float*)d_in[3];
    const float* cb1 = (const float*)d_in[4];
    const float* cw2 = (const float*)d_in[5];
    const float* cb2 = (const float*)d_in[6];
    const float* cw3 = (const float*)d_in[7];
    const float* cb3 = (const float*)d_in[8];
    const float* gn_w = (const float*)d_in[9];
    const float* gn_b = (const float*)d_in[10];
    const float* fw   = (const float*)d_in[11];
    const float* qkw  = (const float*)d_in[12];
    const float* lepe_w = (const float*)d_in[13];
    const float* lepe_b = (const float*)d_in[14];
    float* out = (float*)d_out;

    static bool attr_set = false;
    const int GEMM_SMEM = 2 * 256 * GPITCH * 2;   // 139264 bytes
    if (!attr_set) {
        cudaFuncSetAttribute(k_gemm_tc, cudaFuncAttributeMaxDynamicSharedMemorySize, GEMM_SMEM);
        attr_set = true;
    }

    k_init<<<1024, 256>>>(fw);
    k_wtrans<<<512, 256>>>(qkw);

    dim3 gconv(CN, BN);
    k_conv4<<<gconv, 256>>>(x, cw0, cb0, cw1, cb1, cw2, cb2, cw3, cb3);

    k_fuse<<<BN * CN * NN / 8 / 256, 256>>>(gn_w, gn_b);

    dim3 ggemm(512, 4);
    k_gemm_tc<<<ggemm, 256, GEMM_SMEM>>>();

    k_kmean<<<BN * CN / 8, 256>>>();
    k_z<<<BN * HEADS, 256>>>();

    dim3 gkv(BN * HEADS, 4);
    k_kv<<<gkv, 256>>>();

    k_lepe<<<gconv, 256>>>(lepe_w, lepe_b, out);

    dim3 gattn(BN * HEADS, NN / 64);
    k_attn<<<gattn, 256>>>(out);
}